// round 5
// baseline (speedup 1.0000x reference)
#include <cuda_runtime.h>
#include <math.h>

// Problem constants (from setup_inputs; p_sample=100 fixed)
#define Bn   512
#define Kd   256
#define KH   128
#define Gg   384     // 3*KH
#define Tt   101     // p_sample+1
#define Ff   16
#define MGX  (Bn*Tt)   // 51712 = 404*128 exactly
#define GXB2 (MGX/128) // 404 gemm m-tiles
#define CPB  148       // copy blocks fused into k_gx

// ---------------- packed fp32x2 helpers (sm_103a FFMA2) ----------------
typedef unsigned long long ull;
__device__ __forceinline__ ull ff2(ull a, ull b, ull c) {
    ull d;
    asm("fma.rn.f32x2 %0, %1, %2, %3;" : "=l"(d) : "l"(a), "l"(b), "l"(c));
    return d;
}
__device__ __forceinline__ ull dup2(float x) {
    ull r; asm("mov.b64 %0, {%1, %1};" : "=l"(r) : "f"(x)); return r;
}
__device__ __forceinline__ float2 unpk2(ull v) {
    float2 r; asm("mov.b64 {%0, %1}, %2;" : "=f"(r.x), "=f"(r.y) : "l"(v)); return r;
}
__device__ __forceinline__ float fast_sigmoid(float x) {
    return 1.f / (1.f + __expf(-x));
}
__device__ __forceinline__ float fast_tanh(float x) {
    float e = __expf(2.f * x);
    return 1.f - 2.f / (e + 1.f);
}

// ---------------- scratch (device globals: allocation-free) ----------------
__device__ __align__(16) float g_gx[MGX * Gg];          // [m=b*101+t][g]
__device__ __align__(16) float g_WihT[Kd * Gg];         // [k][g]
__device__ __align__(16) float g_WkT[Ff * KH * Kd];     // [f][h][k]
__device__ __align__(16) float g_ctT[KH * Bn];          // [h][b]
__device__ __align__(16) float g_predT[Ff * Kd * Bn];   // [f][k][c]
__device__ __align__(16) float g_encT[Ff * Kd * Bn];    // [f][k][b]
__device__ __align__(16) float g_totals[Ff * Bn * Bn];  // [f][b][c]
__device__ float g_lse15[Bn];
__device__ float g_diag[Ff * Bn];
__device__ int   g_ok[Bn];

// ---------------- weight transposes (tiny) ----------------
__global__ void k_transpose_wih(const float* __restrict__ W) {
    int idx = blockIdx.x * 256 + threadIdx.x;           // 384*256
    if (idx < Gg * Kd) {
        int g = idx / Kd, k = idx % Kd;
        g_WihT[k * Gg + g] = W[idx];
    }
}
__global__ void k_transpose_wk(const float* __restrict__ W) {
    int idx = blockIdx.x * 256 + threadIdx.x;           // 16*256*128
    if (idx < Ff * Kd * KH) {
        int f = idx >> 15, r = idx & 32767, k = r >> 7, h = r & 127;
        g_WkT[f * (KH * Kd) + h * Kd + k] = W[idx];
    }
}

// ---------------- encoded gather: encT[f][k][b] = z[b][k][101+f] -----------
__global__ void k_enc(const float* __restrict__ z) {
    int idx = blockIdx.x * 256 + threadIdx.x;    // 16*256*512
    if (idx < Ff * Kd * Bn) {
        int b = idx & 511, k = (idx >> 9) & 255, f = idx >> 17;
        g_encT[idx] = z[(size_t)b * (Kd * 256) + k * 256 + (Tt + f)];
    }
}

// =========== 128x128 tile core, 512 threads, 4m x 8n per thread ============
__device__ __forceinline__ void tile_compute512(const float* As, const float* Bs,
                                                int ty, int tx, ull acc[2][8]) {
#pragma unroll
    for (int k = 0; k < 16; k++) {
        ulonglong2 a01 = *(const ulonglong2*)(As + k * 128 + ty * 4);
        float4 b0 = *(const float4*)(Bs + k * 128 + tx * 8);
        float4 b1 = *(const float4*)(Bs + k * 128 + tx * 8 + 4);
        ull bb[8] = {dup2(b0.x), dup2(b0.y), dup2(b0.z), dup2(b0.w),
                     dup2(b1.x), dup2(b1.y), dup2(b1.z), dup2(b1.w)};
#pragma unroll
        for (int j = 0; j < 8; j++) {
            acc[0][j] = ff2(a01.x, bb[j], acc[0][j]);
            acc[1][j] = ff2(a01.y, bb[j], acc[1][j]);
        }
    }
}

// ---------------- gx = seq @ W_ih^T + b_ih  + fused FULL copy ---------------
// Copy uses float2: destination (out+2) is only 8-byte aligned!
__global__ __launch_bounds__(512, 2) void k_gx(const float* __restrict__ z,
                                               const float* __restrict__ bih,
                                               const float2* __restrict__ cpA,
                                               const float2* __restrict__ cpB,
                                               float2* __restrict__ cpDst) {
    if (blockIdx.x >= GXB2) {
        if (blockIdx.y != 0) return;
        const long n2 = (long)Bn * Kd * 256 / 2;     // 16,777,216 float2 per tensor
        long i = (blockIdx.x - GXB2) * 512L + threadIdx.x;
        const long stride = (long)CPB * 512;
        for (; i < n2; i += stride) {
            cpDst[i]      = cpA[i];
            cpDst[i + n2] = cpB[i];
        }
        return;
    }

    __shared__ __align__(16) float As[2][16 * 128];
    __shared__ __align__(16) float Bs[2][16 * 128];
    int tid = threadIdx.x;
    int m0 = blockIdx.x * 128, n0 = blockIdx.y * 128;

    int mA = m0 + (tid & 127);
    int kb = tid >> 7;                         // 0..3
    int bq = mA / Tt, tq = mA - bq * Tt;
    const float* aptr = z + (size_t)bq * (Kd * 256) + tq;
    int nB = n0 + (tid & 127);
    int tx = tid & 15, ty = tid >> 4;

    ull acc[2][8];
#pragma unroll
    for (int i = 0; i < 2; i++)
#pragma unroll
        for (int j = 0; j < 8; j++) acc[i][j] = 0ULL;

    float rA[4], rB[4];
#pragma unroll
    for (int i = 0; i < 4; i++) {
        int kl = kb + 4 * i;
        rA[i] = aptr[(size_t)kl * 256];
        rB[i] = g_WihT[kl * Gg + nB];
    }

    int p = 0;
    for (int kt = 0; kt < Kd; kt += 16) {
#pragma unroll
        for (int i = 0; i < 4; i++) {
            int kl = kb + 4 * i;
            As[p][kl * 128 + (tid & 127)] = rA[i];
            Bs[p][kl * 128 + (tid & 127)] = rB[i];
        }
        __syncthreads();
        if (kt + 16 < Kd) {
#pragma unroll
            for (int i = 0; i < 4; i++) {
                int kl = kt + 16 + kb + 4 * i;
                rA[i] = aptr[(size_t)kl * 256];
                rB[i] = g_WihT[kl * Gg + nB];
            }
        }
        tile_compute512(As[p], Bs[p], ty, tx, acc);
        p ^= 1;
    }
    float4 ba = *(const float4*)&bih[n0 + tx * 8];
    float4 bbv = *(const float4*)&bih[n0 + tx * 8 + 4];
    float bias[8] = {ba.x, ba.y, ba.z, ba.w, bbv.x, bbv.y, bbv.z, bbv.w};
#pragma unroll
    for (int i = 0; i < 2; i++) {
        int mlo = m0 + ty * 4 + 2 * i;
        float2 c[8];
#pragma unroll
        for (int j = 0; j < 8; j++) c[j] = unpk2(acc[i][j]);
        float4 vlo0 = {c[0].x + bias[0], c[1].x + bias[1], c[2].x + bias[2], c[3].x + bias[3]};
        float4 vlo1 = {c[4].x + bias[4], c[5].x + bias[5], c[6].x + bias[6], c[7].x + bias[7]};
        float4 vhi0 = {c[0].y + bias[0], c[1].y + bias[1], c[2].y + bias[2], c[3].y + bias[3]};
        float4 vhi1 = {c[4].y + bias[4], c[5].y + bias[5], c[6].y + bias[6], c[7].y + bias[7]};
        *(float4*)&g_gx[(size_t)mlo * Gg + n0 + tx * 8]           = vlo0;
        *(float4*)&g_gx[(size_t)mlo * Gg + n0 + tx * 8 + 4]       = vlo1;
        *(float4*)&g_gx[(size_t)(mlo + 1) * Gg + n0 + tx * 8]     = vhi0;
        *(float4*)&g_gx[(size_t)(mlo + 1) * Gg + n0 + tx * 8 + 4] = vhi1;
    }
}

// ---------------- persistent GRU: 128 CTAs x 4 rows x 101 steps -------------
// 768 threads: thread = (gate g, half). 4 FFMA2 chains (2 rows x A/B) fits 85 regs.
__global__ __launch_bounds__(768, 1) void k_gru(const float* __restrict__ h0,
                                                const float* __restrict__ Whh,
                                                const float* __restrict__ bhh) {
    __shared__ __align__(16) float h_sm[4][128];
    __shared__ float gh_sm[4][Gg];
    __shared__ float bh_sm[Gg];
    int tid = threadIdx.x;
    int b0 = blockIdx.x * 4;
    int g = tid >> 1, half = tid & 1;

    // 64 weights as 32 packed pairs (64 regs)
    ull w2[32];
    {
        const ulonglong2* wp = (const ulonglong2*)(Whh + g * KH + half * 64);
#pragma unroll
        for (int i = 0; i < 16; i++) {
            ulonglong2 v = wp[i];
            w2[2 * i] = v.x; w2[2 * i + 1] = v.y;
        }
    }

    if (tid < Gg) bh_sm[tid] = bhh[tid];
    int r2 = tid >> 7, j2 = tid & 127;         // valid for tid<512
    if (tid < 512) h_sm[r2][j2] = h0[(b0 + r2) * KH + j2];
    __syncthreads();

    const size_t gxbase = (size_t)(b0 + r2) * Tt * Gg;
    for (int t = 0; t < Tt; t++) {
        // prefetch this step's gx (used only after barrier -> latency hidden)
        float xr = 0.f, xz = 0.f, xn = 0.f;
        if (tid < 512) {
            const float* gp = g_gx + gxbase + (size_t)t * Gg;
            xr = gp[j2]; xz = gp[128 + j2]; xn = gp[256 + j2];
        }
        // phase 1: two row-pairs, 4 interleaved FFMA2 chains each
#pragma unroll
        for (int rp = 0; rp < 4; rp += 2) {
            ull aA0 = 0ULL, aB0 = 0ULL, aA1 = 0ULL, aB1 = 0ULL;
            const ulonglong2* pa = (const ulonglong2*)&h_sm[rp][half * 64];
            const ulonglong2* pb = (const ulonglong2*)&h_sm[rp + 1][half * 64];
#pragma unroll
            for (int i = 0; i < 16; i++) {
                ulonglong2 ha = pa[i], hb = pb[i];
                ull wa = w2[2 * i], wb = w2[2 * i + 1];
                aA0 = ff2(wa, ha.x, aA0); aB0 = ff2(wb, ha.y, aB0);
                aA1 = ff2(wa, hb.x, aA1); aB1 = ff2(wb, hb.y, aB1);
            }
            float2 sa0 = unpk2(aA0), sb0 = unpk2(aB0);
            float2 sa1 = unpk2(aA1), sb1 = unpk2(aB1);
            float v0 = (sa0.x + sa0.y) + (sb0.x + sb0.y);
            float v1 = (sa1.x + sa1.y) + (sb1.x + sb1.y);
            v0 += __shfl_xor_sync(0xffffffffu, v0, 1);
            v1 += __shfl_xor_sync(0xffffffffu, v1, 1);
            if (half == 0) {
                gh_sm[rp][g]     = v0;
                gh_sm[rp + 1][g] = v1;
            }
        }
        __syncthreads();
        // phase 2: gates + state update
        if (tid < 512) {
            float hr = gh_sm[r2][j2]       + bh_sm[j2];
            float hz = gh_sm[r2][128 + j2] + bh_sm[128 + j2];
            float hn = gh_sm[r2][256 + j2] + bh_sm[256 + j2];
            float rr = fast_sigmoid(xr + hr);
            float zz = fast_sigmoid(xz + hz);
            float nn = fast_tanh(xn + rr * hn);
            float hp = h_sm[r2][j2];
            h_sm[r2][j2] = (1.f - zz) * nn + zz * hp;
        }
        __syncthreads();
    }
    if (tid < 512) g_ctT[j2 * Bn + (b0 + r2)] = h_sm[r2][j2];
}

// ------------- generic batched GEMM: C[m][n] = sum_k A[k][m]*B[k][n] --------
__global__ __launch_bounds__(512, 2) void k_gemm(const float* __restrict__ A,
                                                 const float* __restrict__ Bm,
                                                 float* __restrict__ C,
                                                 int lda, int ldb, int ldc, int KK,
                                                 long sA, long sB, long sC,
                                                 const float* __restrict__ rowBias, int sBias) {
    __shared__ __align__(16) float As[2][16 * 128];
    __shared__ __align__(16) float Bs[2][16 * 128];
    int f = blockIdx.z;
    A += (long)f * sA; Bm += (long)f * sB; C += (long)f * sC;
    int tid = threadIdx.x;
    int m0 = blockIdx.y * 128, n0 = blockIdx.x * 128;
    int mA = m0 + (tid & 127), kb = tid >> 7;
    int nB = n0 + (tid & 127);
    int tx = tid & 15, ty = tid >> 4;

    ull acc[2][8];
#pragma unroll
    for (int i = 0; i < 2; i++)
#pragma unroll
        for (int j = 0; j < 8; j++) acc[i][j] = 0ULL;

    float rA[4], rB[4];
#pragma unroll
    for (int i = 0; i < 4; i++) {
        int kl = kb + 4 * i;
        rA[i] = A[(long)kl * lda + mA];
        rB[i] = Bm[(long)kl * ldb + nB];
    }

    int p = 0;
    for (int kt = 0; kt < KK; kt += 16) {
#pragma unroll
        for (int i = 0; i < 4; i++) {
            int kl = kb + 4 * i;
            As[p][kl * 128 + (tid & 127)] = rA[i];
            Bs[p][kl * 128 + (tid & 127)] = rB[i];
        }
        __syncthreads();
        if (kt + 16 < KK) {
#pragma unroll
            for (int i = 0; i < 4; i++) {
                int kl = kt + 16 + kb + 4 * i;
                rA[i] = A[(long)kl * lda + mA];
                rB[i] = Bm[(long)kl * ldb + nB];
            }
        }
        tile_compute512(As[p], Bs[p], ty, tx, acc);
        p ^= 1;
    }
#pragma unroll
    for (int i = 0; i < 2; i++) {
        int mlo = m0 + ty * 4 + 2 * i;
        float blo = rowBias ? rowBias[(long)f * sBias + mlo] : 0.f;
        float bhi = rowBias ? rowBias[(long)f * sBias + mlo + 1] : 0.f;
        float2 c[8];
#pragma unroll
        for (int j = 0; j < 8; j++) c[j] = unpk2(acc[i][j]);
        float4 vlo0 = {c[0].x + blo, c[1].x + blo, c[2].x + blo, c[3].x + blo};
        float4 vlo1 = {c[4].x + blo, c[5].x + blo, c[6].x + blo, c[7].x + blo};
        float4 vhi0 = {c[0].y + bhi, c[1].y + bhi, c[2].y + bhi, c[3].y + bhi};
        float4 vhi1 = {c[4].y + bhi, c[5].y + bhi, c[6].y + bhi, c[7].y + bhi};
        *(float4*)&C[(long)mlo * ldc + n0 + tx * 8]           = vlo0;
        *(float4*)&C[(long)mlo * ldc + n0 + tx * 8 + 4]       = vlo1;
        *(float4*)&C[(long)(mlo + 1) * ldc + n0 + tx * 8]     = vhi0;
        *(float4*)&C[(long)(mlo + 1) * ldc + n0 + tx * 8 + 4] = vhi1;
    }
}

// ---------------- per-row logsumexp + diagonal of log_softmax --------------
__global__ void k_lse() {
    int row = blockIdx.x;                       // f*512 + b
    const float* p = g_totals + (size_t)row * Bn;
    int tid = threadIdx.x;                      // 128
    __shared__ float sm[128];
    float mx = -1e30f;
    for (int c = tid; c < Bn; c += 128) mx = fmaxf(mx, p[c]);
    sm[tid] = mx; __syncthreads();
    for (int s = 64; s; s >>= 1) { if (tid < s) sm[tid] = fmaxf(sm[tid], sm[tid + s]); __syncthreads(); }
    mx = sm[0]; __syncthreads();
    float sum = 0.f;
    for (int c = tid; c < Bn; c += 128) sum += expf(p[c] - mx);
    sm[tid] = sum; __syncthreads();
    for (int s = 64; s; s >>= 1) { if (tid < s) sm[tid] += sm[tid + s]; __syncthreads(); }
    if (tid == 0) {
        float lse = mx + logf(sm[0]);
        int b = row & 511, f = row >> 9;
        g_diag[row] = p[b] - lse;
        if (f == Ff - 1) g_lse15[b] = lse;
    }
}

// ---------------- accuracy: argmax over b of softmax column ----------------
__global__ void k_acc() {
    int c = blockIdx.x;
    const float* p = g_totals + (size_t)(Ff - 1) * Bn * Bn;
    int tid = threadIdx.x;                      // 128
    float best = -1e30f; int bi = 1 << 30;
    for (int b = tid; b < Bn; b += 128) {
        float v = p[(size_t)b * Bn + c] - g_lse15[b];
        if (v > best) { best = v; bi = b; }
    }
    __shared__ float sv[128]; __shared__ int si[128];
    sv[tid] = best; si[tid] = bi; __syncthreads();
    for (int s = 64; s; s >>= 1) {
        if (tid < s) {
            float v2 = sv[tid + s]; int i2 = si[tid + s];
            if (v2 > sv[tid] || (v2 == sv[tid] && i2 < si[tid])) { sv[tid] = v2; si[tid] = i2; }
        }
        __syncthreads();
    }
    if (tid == 0) g_ok[c] = (si[0] == c) ? 1 : 0;
}

// ---------------- deterministic final reduction -----------------------------
__global__ void k_final(float* __restrict__ out) {
    __shared__ float s[256]; __shared__ int si[256];
    int tid = threadIdx.x;
    float sum = 0.f;
    for (int i = tid; i < Ff * Bn; i += 256) sum += g_diag[i];
    int cnt = 0;
    for (int i = tid; i < Bn; i += 256) cnt += g_ok[i];
    s[tid] = sum; si[tid] = cnt; __syncthreads();
    for (int st = 128; st; st >>= 1) {
        if (tid < st) { s[tid] += s[tid + st]; si[tid] += si[tid + st]; }
        __syncthreads();
    }
    if (tid == 0) {
        out[0] = (float)si[0] / (float)Bn;               // accuracy
        out[1] = -s[0] / (float)(Ff * Bn);               // nce
    }
}

// ---------------- host ----------------
extern "C" void kernel_launch(void* const* d_in, const int* in_sizes, int n_in,
                              void* d_out, int out_size) {
    const float* zqst   = (const float*)d_in[0];
    const float* zex    = (const float*)d_in[1];
    const float* zqx    = (const float*)d_in[2];
    const float* hidden = (const float*)d_in[3];
    const float* Wih = (const float*)d_in[4];
    const float* Whh = (const float*)d_in[5];
    const float* bih = (const float*)d_in[6];
    const float* bhh = (const float*)d_in[7];
    const float* Wkw = (const float*)d_in[8];
    const float* Wkb = (const float*)d_in[9];
    float* out = (float*)d_out;

    float *p_wkT, *p_ctT, *p_predT, *p_encT, *p_totals;
    cudaGetSymbolAddress((void**)&p_wkT,    g_WkT);
    cudaGetSymbolAddress((void**)&p_ctT,    g_ctT);
    cudaGetSymbolAddress((void**)&p_predT,  g_predT);
    cudaGetSymbolAddress((void**)&p_encT,   g_encT);
    cudaGetSymbolAddress((void**)&p_totals, g_totals);

    k_transpose_wih<<<(Gg * Kd + 255) / 256, 256>>>(Wih);
    k_transpose_wk<<<(Ff * Kd * KH + 255) / 256, 256>>>(Wkw);
    k_enc<<<(Ff * Kd * Bn + 255) / 256, 256>>>(zqst);

    // gx GEMM + full passthrough copy on extra blocks (float2: dst is 8B-aligned)
    k_gx<<<dim3(GXB2 + CPB, Gg / 128), 512>>>(zqst, bih,
        (const float2*)zex, (const float2*)zqx, (float2*)(out + 2));

    // GRU (no copy fusion)
    k_gru<<<Bn / 4, 768>>>(hidden, Whh, bhh);

    // predT[f][k][c] = sum_h WkT[f][h][k] * ctT[h][c] + Wk_b[f][k]
    k_gemm<<<dim3(Bn / 128, Kd / 128, Ff), 512>>>(p_wkT, p_ctT, p_predT,
        Kd, Bn, Bn, KH, (long)KH * Kd, 0L, (long)Kd * Bn, Wkb, Kd);
    // totals[f][b][c] = sum_k encT[f][k][b] * predT[f][k][c]
    k_gemm<<<dim3(Bn / 128, Bn / 128, Ff), 512>>>(p_encT, p_predT, p_totals,
        Bn, Bn, Bn, Kd, (long)Kd * Bn, (long)Kd * Bn, (long)Bn * Bn, nullptr, 0);

    k_lse<<<Ff * Bn, 128>>>();
    k_acc<<<Bn, 128>>>();
    k_final<<<1, 256>>>(out);
}

// round 6
// speedup vs baseline: 1.2000x; 1.2000x over previous
#include <cuda_runtime.h>
#include <math.h>

// Problem constants (from setup_inputs; p_sample=100 fixed)
#define Bn   512
#define Kd   256
#define KH   128
#define Gg   384     // 3*KH
#define Tt   101     // p_sample+1
#define Ff   16
#define MGX  (Bn*Tt) // 51712 = 808*64 exactly
#define GXB  (MGX/64)  // 808 gemm blocks along m
#define CPB  256       // copy blocks fused into k_gx

// ---------------- packed fp32x2 helpers (sm_103a FFMA2) ----------------
typedef unsigned long long ull;
__device__ __forceinline__ ull ff2(ull a, ull b, ull c) {
    ull d;
    asm("fma.rn.f32x2 %0, %1, %2, %3;" : "=l"(d) : "l"(a), "l"(b), "l"(c));
    return d;
}
__device__ __forceinline__ ull dup2(float x) {
    ull r; asm("mov.b64 %0, {%1, %1};" : "=l"(r) : "f"(x)); return r;
}
__device__ __forceinline__ float2 unpk2(ull v) {
    float2 r; asm("mov.b64 {%0, %1}, %2;" : "=f"(r.x), "=f"(r.y) : "l"(v)); return r;
}
__device__ __forceinline__ float fast_sigmoid(float x) {
    return 1.f / (1.f + __expf(-x));
}
__device__ __forceinline__ float fast_tanh(float x) {
    float e = __expf(2.f * x);
    return 1.f - 2.f / (e + 1.f);
}

// ---------------- scratch (device globals: allocation-free) ----------------
__device__ __align__(16) float g_gx[MGX * Gg];          // [m=b*101+t][g]
__device__ __align__(16) float g_WihT[Kd * Gg];         // [k][g]
__device__ __align__(16) float g_WkT[Ff * KH * Kd];     // [f][h][k]
__device__ __align__(16) float g_ctT[KH * Bn];          // [h][b]
__device__ __align__(16) float g_predT[Ff * Kd * Bn];   // [f][k][c]
__device__ __align__(16) float g_encT[Ff * Kd * Bn];    // [f][k][b]
__device__ __align__(16) float g_totals[Ff * Bn * Bn];  // [f][b][c]
__device__ float g_lse15[Bn];
__device__ float g_diag[Ff * Bn];
__device__ int   g_ok[Bn];

// ---------------- weight transposes (tiny) ----------------
__global__ void k_transpose_wih(const float* __restrict__ W) {
    int idx = blockIdx.x * 256 + threadIdx.x;           // 384*256
    if (idx < Gg * Kd) {
        int g = idx / Kd, k = idx % Kd;
        g_WihT[k * Gg + g] = W[idx];
    }
}
__global__ void k_transpose_wk(const float* __restrict__ W) {
    int idx = blockIdx.x * 256 + threadIdx.x;           // 16*256*128
    if (idx < Ff * Kd * KH) {
        int f = idx >> 15, r = idx & 32767, k = r >> 7, h = r & 127;
        g_WkT[f * (KH * Kd) + h * Kd + k] = W[idx];
    }
}

// ---------------- encoded gather: encT[f][k][b] = z[b][k][101+f] -----------
__global__ void k_enc(const float* __restrict__ z) {
    int idx = blockIdx.x * 256 + threadIdx.x;    // 16*256*512
    if (idx < Ff * Kd * Bn) {
        int b = idx & 511, k = (idx >> 9) & 255, f = idx >> 17;
        g_encT[idx] = z[(size_t)b * (Kd * 256) + k * 256 + (Tt + f)];
    }
}

// ---------------- gx = seq @ W_ih^T + b_ih  + fused passthrough copy -------
// (round-2 proven config: 256 thr, 64x128 tile, fma ~52%, 255us incl copy)
__global__ __launch_bounds__(256) void k_gx(const float* __restrict__ z,
                                            const float* __restrict__ bih,
                                            const float2* __restrict__ cpA,
                                            const float2* __restrict__ cpB,
                                            float2* __restrict__ cpDst) {
    if (blockIdx.x >= GXB) {
        if (blockIdx.y != 0) return;
        const long n2 = (long)Bn * Kd * 256 / 2;
        long i = (blockIdx.x - GXB) * 256L + threadIdx.x;
        const long stride = (long)CPB * 256;
        for (; i < n2; i += stride) {
            cpDst[i]      = cpA[i];
            cpDst[i + n2] = cpB[i];
        }
        return;
    }

    __shared__ __align__(16) float As[32][64];
    __shared__ __align__(16) float Bs[32][128];
    int tid = threadIdx.x;
    int m0 = blockIdx.x * 64, n0 = blockIdx.y * 128;

    int mA = m0 + (tid & 63);
    int kA0 = tid >> 6;                       // 0..3
    int bq = mA / Tt, tq = mA - bq * Tt;      // fixed per thread
    const float* aptr = z + (size_t)bq * (Kd * 256) + tq;

    int nB = n0 + (tid & 127);
    int kB0 = tid >> 7;                       // 0..1
    int tx = tid & 31, ty = tid >> 5;

    ull acc[4][4];                             // [m-pair][n], packed along m
#pragma unroll
    for (int i = 0; i < 4; i++)
#pragma unroll
        for (int j = 0; j < 4; j++) acc[i][j] = 0ULL;

    for (int kt = 0; kt < Kd; kt += 32) {
#pragma unroll
        for (int i = 0; i < 8; i++) {
            int kl = kA0 + 4 * i;
            As[kl][tid & 63] = aptr[(size_t)(kt + kl) * 256];
        }
#pragma unroll
        for (int i = 0; i < 16; i++) {
            int kl = kB0 + 2 * i;
            Bs[kl][tid & 127] = g_WihT[(kt + kl) * Gg + nB];
        }
        __syncthreads();
#pragma unroll
        for (int k = 0; k < 32; k++) {
            ulonglong2 a0 = *(const ulonglong2*)&As[k][ty * 8];
            ulonglong2 a1 = *(const ulonglong2*)&As[k][ty * 8 + 4];
            float4 b4 = *(const float4*)&Bs[k][tx * 4];
            ull bb[4] = {dup2(b4.x), dup2(b4.y), dup2(b4.z), dup2(b4.w)};
            ull am[4] = {a0.x, a0.y, a1.x, a1.y};
#pragma unroll
            for (int i = 0; i < 4; i++)
#pragma unroll
                for (int j = 0; j < 4; j++) acc[i][j] = ff2(am[i], bb[j], acc[i][j]);
        }
        __syncthreads();
    }
    float4 bias = *(const float4*)&bih[n0 + tx * 4];
#pragma unroll
    for (int i = 0; i < 4; i++) {
        float2 c0 = unpk2(acc[i][0]), c1 = unpk2(acc[i][1]);
        float2 c2 = unpk2(acc[i][2]), c3 = unpk2(acc[i][3]);
        int mlo = m0 + ty * 8 + 2 * i;
        float4 vlo = {c0.x + bias.x, c1.x + bias.y, c2.x + bias.z, c3.x + bias.w};
        float4 vhi = {c0.y + bias.x, c1.y + bias.y, c2.y + bias.z, c3.y + bias.w};
        *(float4*)&g_gx[(size_t)mlo * Gg + n0 + tx * 4] = vlo;
        *(float4*)&g_gx[(size_t)(mlo + 1) * Gg + n0 + tx * 4] = vhi;
    }
}

// ---------------- persistent GRU: 128 CTAs x 4 rows x 101 steps ------------
// Round-1 register structure (80 regs, NO SPILLS) + FFMA2 inner loop.
// Per thread: w2[32] (64 regs) + 2 acc chains + minimal staging ~= 84 regs.
__global__ __launch_bounds__(768, 1) void k_gru(const float* __restrict__ h0,
                                                const float* __restrict__ Whh,
                                                const float* __restrict__ bhh) {
    __shared__ __align__(16) float h_sm[4][128];
    __shared__ float gh_sm[4][Gg];
    __shared__ float bh_sm[Gg];
    int tid = threadIdx.x;
    int b0 = blockIdx.x * 4;
    int g = tid >> 1, half = tid & 1;

    // cache this thread's 64 W_hh weights as 32 packed fp32 pairs (64 regs)
    ull w2[32];
    {
        const ulonglong2* wp = (const ulonglong2*)(Whh + g * KH + half * 64);
#pragma unroll
        for (int i = 0; i < 16; i++) {
            ulonglong2 v = wp[i];
            w2[2 * i] = v.x; w2[2 * i + 1] = v.y;
        }
    }

    if (tid < Gg) bh_sm[tid] = bhh[tid];
    int r2 = tid >> 7, j2 = tid & 127;         // valid for tid<512
    if (tid < 512) h_sm[r2][j2] = h0[(b0 + r2) * KH + j2];
    __syncthreads();

    const float* gp0 = g_gx + (size_t)(b0 + r2) * Tt * Gg;
    for (int t = 0; t < Tt; t++) {
        // prefetch this step's gx (consumed in phase 2, after the dot products)
        float xr = 0.f, xz = 0.f, xn = 0.f;
        if (tid < 512) {
            const float* gp = gp0 + (size_t)t * Gg;
            xr = gp[j2]; xz = gp[128 + j2]; xn = gp[256 + j2];
        }
        // phase 1: gh[r][g] = h[r,:] . Whh[g,:]  -- one row at a time (low regs)
#pragma unroll
        for (int r = 0; r < 4; r++) {
            ull accA = 0ULL, accB = 0ULL;
            const ulonglong2* hp = (const ulonglong2*)&h_sm[r][half * 64];
#pragma unroll
            for (int i = 0; i < 16; i++) {
                ulonglong2 hv = hp[i];
                accA = ff2(w2[2 * i],     hv.x, accA);
                accB = ff2(w2[2 * i + 1], hv.y, accB);
            }
            float2 sa = unpk2(accA), sb = unpk2(accB);
            float acc = (sa.x + sa.y) + (sb.x + sb.y);
            acc += __shfl_xor_sync(0xffffffffu, acc, 1);
            if (half == 0) gh_sm[r][g] = acc;
        }
        __syncthreads();
        // phase 2: gates + state update
        if (tid < 512) {
            float hr = gh_sm[r2][j2]       + bh_sm[j2];
            float hz = gh_sm[r2][128 + j2] + bh_sm[128 + j2];
            float hn = gh_sm[r2][256 + j2] + bh_sm[256 + j2];
            float rr = fast_sigmoid(xr + hr);
            float zz = fast_sigmoid(xz + hz);
            float nn = fast_tanh(xn + rr * hn);
            float hp = h_sm[r2][j2];
            h_sm[r2][j2] = (1.f - zz) * nn + zz * hp;
        }
        __syncthreads();
    }
    if (tid < 512) g_ctT[j2 * Bn + (b0 + r2)] = h_sm[r2][j2];
}

// ------------- generic batched GEMM (round-2 proven): C=sum_k A[k][m]B[k][n]
__global__ __launch_bounds__(256) void k_gemm(const float* __restrict__ A,
                                              const float* __restrict__ Bm,
                                              float* __restrict__ C,
                                              int lda, int ldb, int ldc, int KK,
                                              long sA, long sB, long sC,
                                              const float* __restrict__ rowBias, int sBias) {
    __shared__ __align__(16) float As[32][64];
    __shared__ __align__(16) float Bs[32][128];
    int f = blockIdx.z;
    A += (long)f * sA; Bm += (long)f * sB; C += (long)f * sC;
    int tid = threadIdx.x;
    int m0 = blockIdx.y * 64, n0 = blockIdx.x * 128;
    int mA = m0 + (tid & 63), kA0 = tid >> 6;
    int nB = n0 + (tid & 127), kB0 = tid >> 7;
    int tx = tid & 31, ty = tid >> 5;
    ull acc[4][4];
#pragma unroll
    for (int i = 0; i < 4; i++)
#pragma unroll
        for (int j = 0; j < 4; j++) acc[i][j] = 0ULL;

    for (int kt = 0; kt < KK; kt += 32) {
#pragma unroll
        for (int i = 0; i < 8; i++) { int kl = kA0 + 4 * i; As[kl][tid & 63] = A[(long)(kt + kl) * lda + mA]; }
#pragma unroll
        for (int i = 0; i < 16; i++) { int kl = kB0 + 2 * i; Bs[kl][tid & 127] = Bm[(long)(kt + kl) * ldb + nB]; }
        __syncthreads();
#pragma unroll
        for (int k = 0; k < 32; k++) {
            ulonglong2 a0 = *(const ulonglong2*)&As[k][ty * 8];
            ulonglong2 a1 = *(const ulonglong2*)&As[k][ty * 8 + 4];
            float4 b4 = *(const float4*)&Bs[k][tx * 4];
            ull bb[4] = {dup2(b4.x), dup2(b4.y), dup2(b4.z), dup2(b4.w)};
            ull am[4] = {a0.x, a0.y, a1.x, a1.y};
#pragma unroll
            for (int i = 0; i < 4; i++)
#pragma unroll
                for (int j = 0; j < 4; j++) acc[i][j] = ff2(am[i], bb[j], acc[i][j]);
        }
        __syncthreads();
    }
#pragma unroll
    for (int i = 0; i < 4; i++) {
        int mlo = m0 + ty * 8 + 2 * i;
        float blo = rowBias ? rowBias[(long)f * sBias + mlo] : 0.f;
        float bhi = rowBias ? rowBias[(long)f * sBias + mlo + 1] : 0.f;
        float2 c0 = unpk2(acc[i][0]), c1 = unpk2(acc[i][1]);
        float2 c2 = unpk2(acc[i][2]), c3 = unpk2(acc[i][3]);
        float4 vlo = {c0.x + blo, c1.x + blo, c2.x + blo, c3.x + blo};
        float4 vhi = {c0.y + bhi, c1.y + bhi, c2.y + bhi, c3.y + bhi};
        *(float4*)&C[(long)mlo * ldc + n0 + tx * 4] = vlo;
        *(float4*)&C[(long)(mlo + 1) * ldc + n0 + tx * 4] = vhi;
    }
}

// ---------------- per-row logsumexp + diagonal of log_softmax --------------
__global__ void k_lse() {
    int row = blockIdx.x;                       // f*512 + b
    const float* p = g_totals + (size_t)row * Bn;
    int tid = threadIdx.x;                      // 128
    __shared__ float sm[128];
    float mx = -1e30f;
    for (int c = tid; c < Bn; c += 128) mx = fmaxf(mx, p[c]);
    sm[tid] = mx; __syncthreads();
    for (int s = 64; s; s >>= 1) { if (tid < s) sm[tid] = fmaxf(sm[tid], sm[tid + s]); __syncthreads(); }
    mx = sm[0]; __syncthreads();
    float sum = 0.f;
    for (int c = tid; c < Bn; c += 128) sum += expf(p[c] - mx);
    sm[tid] = sum; __syncthreads();
    for (int s = 64; s; s >>= 1) { if (tid < s) sm[tid] += sm[tid + s]; __syncthreads(); }
    if (tid == 0) {
        float lse = mx + logf(sm[0]);
        int b = row & 511, f = row >> 9;
        g_diag[row] = p[b] - lse;
        if (f == Ff - 1) g_lse15[b] = lse;
    }
}

// ---------------- accuracy: argmax over b of softmax column ----------------
__global__ void k_acc() {
    int c = blockIdx.x;
    const float* p = g_totals + (size_t)(Ff - 1) * Bn * Bn;
    int tid = threadIdx.x;                      // 128
    float best = -1e30f; int bi = 1 << 30;
    for (int b = tid; b < Bn; b += 128) {
        float v = p[(size_t)b * Bn + c] - g_lse15[b];
        if (v > best) { best = v; bi = b; }
    }
    __shared__ float sv[128]; __shared__ int si[128];
    sv[tid] = best; si[tid] = bi; __syncthreads();
    for (int s = 64; s; s >>= 1) {
        if (tid < s) {
            float v2 = sv[tid + s]; int i2 = si[tid + s];
            if (v2 > sv[tid] || (v2 == sv[tid] && i2 < si[tid])) { sv[tid] = v2; si[tid] = i2; }
        }
        __syncthreads();
    }
    if (tid == 0) g_ok[c] = (si[0] == c) ? 1 : 0;
}

// ---------------- deterministic final reduction -----------------------------
__global__ void k_final(float* __restrict__ out) {
    __shared__ float s[256]; __shared__ int si[256];
    int tid = threadIdx.x;
    float sum = 0.f;
    for (int i = tid; i < Ff * Bn; i += 256) sum += g_diag[i];
    int cnt = 0;
    for (int i = tid; i < Bn; i += 256) cnt += g_ok[i];
    s[tid] = sum; si[tid] = cnt; __syncthreads();
    for (int st = 128; st; st >>= 1) {
        if (tid < st) { s[tid] += s[tid + st]; si[tid] += si[tid + st]; }
        __syncthreads();
    }
    if (tid == 0) {
        out[0] = (float)si[0] / (float)Bn;               // accuracy
        out[1] = -s[0] / (float)(Ff * Bn);               // nce
    }
}

// ---------------- host ----------------
extern "C" void kernel_launch(void* const* d_in, const int* in_sizes, int n_in,
                              void* d_out, int out_size) {
    const float* zqst   = (const float*)d_in[0];
    const float* zex    = (const float*)d_in[1];
    const float* zqx    = (const float*)d_in[2];
    const float* hidden = (const float*)d_in[3];
    const float* Wih = (const float*)d_in[4];
    const float* Whh = (const float*)d_in[5];
    const float* bih = (const float*)d_in[6];
    const float* bhh = (const float*)d_in[7];
    const float* Wkw = (const float*)d_in[8];
    const float* Wkb = (const float*)d_in[9];
    float* out = (float*)d_out;

    float *p_wkT, *p_ctT, *p_predT, *p_encT, *p_totals;
    cudaGetSymbolAddress((void**)&p_wkT,    g_WkT);
    cudaGetSymbolAddress((void**)&p_ctT,    g_ctT);
    cudaGetSymbolAddress((void**)&p_predT,  g_predT);
    cudaGetSymbolAddress((void**)&p_encT,   g_encT);
    cudaGetSymbolAddress((void**)&p_totals, g_totals);

    k_transpose_wih<<<(Gg * Kd + 255) / 256, 256>>>(Wih);
    k_transpose_wk<<<(Ff * Kd * KH + 255) / 256, 256>>>(Wkw);
    k_enc<<<(Ff * Kd * Bn + 255) / 256, 256>>>(zqst);

    // gx GEMM + full passthrough copy (float2 — dst is only 8B aligned)
    k_gx<<<dim3(GXB + CPB, Gg / 128), 256>>>(zqst, bih,
        (const float2*)zex, (const float2*)zqx, (float2*)(out + 2));

    // GRU (no copy fusion, no spills)
    k_gru<<<Bn / 4, 768>>>(hidden, Whh, bhh);

    // predT[f][k][c] = sum_h WkT[f][h][k] * ctT[h][c] + Wk_b[f][k]
    k_gemm<<<dim3(Bn / 128, Kd / 64, Ff), 256>>>(p_wkT, p_ctT, p_predT,
        Kd, Bn, Bn, KH, (long)KH * Kd, 0L, (long)Kd * Bn, Wkb, Kd);
    // totals[f][b][c] = sum_k encT[f][k][b] * predT[f][k][c]
    k_gemm<<<dim3(Bn / 128, Bn / 64, Ff), 256>>>(p_encT, p_predT, p_totals,
        Bn, Bn, Bn, Kd, (long)Kd * Bn, (long)Kd * Bn, (long)Bn * Bn, nullptr, 0);

    k_lse<<<Ff * Bn, 128>>>();
    k_acc<<<Bn, 128>>>();
    k_final<<<1, 256>>>(out);
}

// round 7
// speedup vs baseline: 1.5001x; 1.2500x over previous
#include <cuda_runtime.h>
#include <math.h>

// Problem constants (from setup_inputs; p_sample=100 fixed)
#define Bn   512
#define Kd   256
#define KH   128
#define Gg   384     // 3*KH
#define Tt   101     // p_sample+1
#define Ff   16
#define MGX  (Bn*Tt) // 51712 = 808*64 exactly
#define GXB  (MGX/64)  // 808 gemm blocks along m
#define CPB  256       // copy blocks fused into k_gx

// ---------------- packed fp32x2 helpers (sm_103a FFMA2) ----------------
typedef unsigned long long ull;
__device__ __forceinline__ ull ff2(ull a, ull b, ull c) {
    ull d;
    asm("fma.rn.f32x2 %0, %1, %2, %3;" : "=l"(d) : "l"(a), "l"(b), "l"(c));
    return d;
}
__device__ __forceinline__ ull dup2(float x) {
    ull r; asm("mov.b64 %0, {%1, %1};" : "=l"(r) : "f"(x)); return r;
}
__device__ __forceinline__ float2 unpk2(ull v) {
    float2 r; asm("mov.b64 {%0, %1}, %2;" : "=f"(r.x), "=f"(r.y) : "l"(v)); return r;
}
__device__ __forceinline__ float fast_sigmoid(float x) {
    return 1.f / (1.f + __expf(-x));
}
__device__ __forceinline__ float fast_tanh(float x) {
    float e = __expf(2.f * x);
    return 1.f - 2.f / (e + 1.f);
}

// ---------------- scratch (device globals: allocation-free) ----------------
__device__ __align__(16) float g_gx[MGX * Gg];          // [m=b*101+t][g]
__device__ __align__(16) float g_WihT[Kd * Gg];         // [k][g]
__device__ __align__(16) float g_WkT[Ff * KH * Kd];     // [f][h][k]
__device__ __align__(16) float g_ctT[KH * Bn];          // [h][b]
__device__ __align__(16) float g_predT[Ff * Kd * Bn];   // [f][k][c]
__device__ __align__(16) float g_encT[Ff * Kd * Bn];    // [f][k][b]
__device__ __align__(16) float g_totals[Ff * Bn * Bn];  // [f][b][c]
__device__ float g_lse15[Bn];
__device__ float g_diag[Ff * Bn];
__device__ int   g_ok[Bn];

// ---------------- weight transposes (tiny) ----------------
__global__ void k_transpose_wih(const float* __restrict__ W) {
    int idx = blockIdx.x * 256 + threadIdx.x;           // 384*256
    if (idx < Gg * Kd) {
        int g = idx / Kd, k = idx % Kd;
        g_WihT[k * Gg + g] = W[idx];
    }
}
__global__ void k_transpose_wk(const float* __restrict__ W) {
    int idx = blockIdx.x * 256 + threadIdx.x;           // 16*256*128
    if (idx < Ff * Kd * KH) {
        int f = idx >> 15, r = idx & 32767, k = r >> 7, h = r & 127;
        g_WkT[f * (KH * Kd) + h * Kd + k] = W[idx];
    }
}

// ---------------- encoded gather: encT[f][k][b] = z[b][k][101+f] -----------
__global__ void k_enc(const float* __restrict__ z) {
    int idx = blockIdx.x * 256 + threadIdx.x;    // 16*256*512
    if (idx < Ff * Kd * Bn) {
        int b = idx & 511, k = (idx >> 9) & 255, f = idx >> 17;
        g_encT[idx] = z[(size_t)b * (Kd * 256) + k * 256 + (Tt + f)];
    }
}

// ---------------- gx = seq @ W_ih^T + b_ih  + fused passthrough copy -------
// (round-2/6 proven config: 256 thr, 64x128 tile, fma ~52%, ~255us incl copy)
__global__ __launch_bounds__(256) void k_gx(const float* __restrict__ z,
                                            const float* __restrict__ bih,
                                            const float2* __restrict__ cpA,
                                            const float2* __restrict__ cpB,
                                            float2* __restrict__ cpDst) {
    if (blockIdx.x >= GXB) {
        if (blockIdx.y != 0) return;
        const long n2 = (long)Bn * Kd * 256 / 2;
        long i = (blockIdx.x - GXB) * 256L + threadIdx.x;
        const long stride = (long)CPB * 256;
        for (; i < n2; i += stride) {
            cpDst[i]      = cpA[i];
            cpDst[i + n2] = cpB[i];
        }
        return;
    }

    __shared__ __align__(16) float As[32][64];
    __shared__ __align__(16) float Bs[32][128];
    int tid = threadIdx.x;
    int m0 = blockIdx.x * 64, n0 = blockIdx.y * 128;

    int mA = m0 + (tid & 63);
    int kA0 = tid >> 6;                       // 0..3
    int bq = mA / Tt, tq = mA - bq * Tt;      // fixed per thread
    const float* aptr = z + (size_t)bq * (Kd * 256) + tq;

    int nB = n0 + (tid & 127);
    int kB0 = tid >> 7;                       // 0..1
    int tx = tid & 31, ty = tid >> 5;

    ull acc[4][4];                             // [m-pair][n], packed along m
#pragma unroll
    for (int i = 0; i < 4; i++)
#pragma unroll
        for (int j = 0; j < 4; j++) acc[i][j] = 0ULL;

    for (int kt = 0; kt < Kd; kt += 32) {
#pragma unroll
        for (int i = 0; i < 8; i++) {
            int kl = kA0 + 4 * i;
            As[kl][tid & 63] = aptr[(size_t)(kt + kl) * 256];
        }
#pragma unroll
        for (int i = 0; i < 16; i++) {
            int kl = kB0 + 2 * i;
            Bs[kl][tid & 127] = g_WihT[(kt + kl) * Gg + nB];
        }
        __syncthreads();
#pragma unroll
        for (int k = 0; k < 32; k++) {
            ulonglong2 a0 = *(const ulonglong2*)&As[k][ty * 8];
            ulonglong2 a1 = *(const ulonglong2*)&As[k][ty * 8 + 4];
            float4 b4 = *(const float4*)&Bs[k][tx * 4];
            ull bb[4] = {dup2(b4.x), dup2(b4.y), dup2(b4.z), dup2(b4.w)};
            ull am[4] = {a0.x, a0.y, a1.x, a1.y};
#pragma unroll
            for (int i = 0; i < 4; i++)
#pragma unroll
                for (int j = 0; j < 4; j++) acc[i][j] = ff2(am[i], bb[j], acc[i][j]);
        }
        __syncthreads();
    }
    float4 bias = *(const float4*)&bih[n0 + tx * 4];
#pragma unroll
    for (int i = 0; i < 4; i++) {
        float2 c0 = unpk2(acc[i][0]), c1 = unpk2(acc[i][1]);
        float2 c2 = unpk2(acc[i][2]), c3 = unpk2(acc[i][3]);
        int mlo = m0 + ty * 8 + 2 * i;
        float4 vlo = {c0.x + bias.x, c1.x + bias.y, c2.x + bias.z, c3.x + bias.w};
        float4 vhi = {c0.y + bias.x, c1.y + bias.y, c2.y + bias.z, c3.y + bias.w};
        *(float4*)&g_gx[(size_t)mlo * Gg + n0 + tx * 4] = vlo;
        *(float4*)&g_gx[(size_t)(mlo + 1) * Gg + n0 + tx * 4] = vhi;
    }
}

// ---------------- persistent GRU v2: warp-uniform halves --------------------
// 768 threads: tid = half*384 + g  => each warp is single-half, so every
// LDS of h_sm is a TRUE single-address broadcast (1 l1tex wavefront).
// Partial dots combined through gh2[r][half][g] in smem (no shfl).
__global__ __launch_bounds__(768, 1) void k_gru(const float* __restrict__ h0,
                                                const float* __restrict__ Whh,
                                                const float* __restrict__ bhh) {
    __shared__ __align__(16) float h_sm[4][128];
    __shared__ float gh2[4][2][Gg];
    __shared__ float bh_sm[Gg];
    int tid = threadIdx.x;
    int b0 = blockIdx.x * 4;
    int half = (tid >= Gg) ? 1 : 0;
    int g = tid - half * Gg;

    // cache this thread's 64 W_hh weights as 32 packed fp32 pairs (64 regs)
    ull w2[32];
    {
        const ulonglong2* wp = (const ulonglong2*)(Whh + g * KH + half * 64);
#pragma unroll
        for (int i = 0; i < 16; i++) {
            ulonglong2 v = wp[i];
            w2[2 * i] = v.x; w2[2 * i + 1] = v.y;
        }
    }

    if (tid < Gg) bh_sm[tid] = bhh[tid];
    int r2 = tid >> 7, j2 = tid & 127;         // valid for tid<512
    if (tid < 512) h_sm[r2][j2] = h0[(b0 + r2) * KH + j2];
    __syncthreads();

    const float* gp0 = g_gx + (size_t)(b0 + r2) * Tt * Gg;
    for (int t = 0; t < Tt; t++) {
        // prefetch this step's gx (consumed in phase 2)
        float xr = 0.f, xz = 0.f, xn = 0.f;
        if (tid < 512) {
            const float* gp = gp0 + (size_t)t * Gg;
            xr = gp[j2]; xz = gp[128 + j2]; xn = gp[256 + j2];
        }
        // phase 1: partial dot for (row r, gate g, half) -- all LDS broadcast
#pragma unroll
        for (int r = 0; r < 4; r++) {
            ull accA = 0ULL, accB = 0ULL;
            const ulonglong2* hp = (const ulonglong2*)&h_sm[r][half * 64];
#pragma unroll
            for (int i = 0; i < 16; i++) {
                ulonglong2 hv = hp[i];           // warp-uniform address
                accA = ff2(w2[2 * i],     hv.x, accA);
                accB = ff2(w2[2 * i + 1], hv.y, accB);
            }
            float2 sa = unpk2(accA), sb = unpk2(accB);
            gh2[r][half][g] = (sa.x + sa.y) + (sb.x + sb.y);
        }
        __syncthreads();
        // phase 2: combine halves, gates + state update
        if (tid < 512) {
            float hr = gh2[r2][0][j2]       + gh2[r2][1][j2]       + bh_sm[j2];
            float hz = gh2[r2][0][128 + j2] + gh2[r2][1][128 + j2] + bh_sm[128 + j2];
            float hn = gh2[r2][0][256 + j2] + gh2[r2][1][256 + j2] + bh_sm[256 + j2];
            float rr = fast_sigmoid(xr + hr);
            float zz = fast_sigmoid(xz + hz);
            float nn = fast_tanh(xn + rr * hn);
            float hp = h_sm[r2][j2];
            h_sm[r2][j2] = (1.f - zz) * nn + zz * hp;
        }
        __syncthreads();
    }
    if (tid < 512) g_ctT[j2 * Bn + (b0 + r2)] = h_sm[r2][j2];
}

// ------------- generic batched GEMM (round-2 proven): C=sum_k A[k][m]B[k][n]
__global__ __launch_bounds__(256) void k_gemm(const float* __restrict__ A,
                                              const float* __restrict__ Bm,
                                              float* __restrict__ C,
                                              int lda, int ldb, int ldc, int KK,
                                              long sA, long sB, long sC,
                                              const float* __restrict__ rowBias, int sBias) {
    __shared__ __align__(16) float As[32][64];
    __shared__ __align__(16) float Bs[32][128];
    int f = blockIdx.z;
    A += (long)f * sA; Bm += (long)f * sB; C += (long)f * sC;
    int tid = threadIdx.x;
    int m0 = blockIdx.y * 64, n0 = blockIdx.x * 128;
    int mA = m0 + (tid & 63), kA0 = tid >> 6;
    int nB = n0 + (tid & 127), kB0 = tid >> 7;
    int tx = tid & 31, ty = tid >> 5;
    ull acc[4][4];
#pragma unroll
    for (int i = 0; i < 4; i++)
#pragma unroll
        for (int j = 0; j < 4; j++) acc[i][j] = 0ULL;

    for (int kt = 0; kt < KK; kt += 32) {
#pragma unroll
        for (int i = 0; i < 8; i++) { int kl = kA0 + 4 * i; As[kl][tid & 63] = A[(long)(kt + kl) * lda + mA]; }
#pragma unroll
        for (int i = 0; i < 16; i++) { int kl = kB0 + 2 * i; Bs[kl][tid & 127] = Bm[(long)(kt + kl) * ldb + nB]; }
        __syncthreads();
#pragma unroll
        for (int k = 0; k < 32; k++) {
            ulonglong2 a0 = *(const ulonglong2*)&As[k][ty * 8];
            ulonglong2 a1 = *(const ulonglong2*)&As[k][ty * 8 + 4];
            float4 b4 = *(const float4*)&Bs[k][tx * 4];
            ull bb[4] = {dup2(b4.x), dup2(b4.y), dup2(b4.z), dup2(b4.w)};
            ull am[4] = {a0.x, a0.y, a1.x, a1.y};
#pragma unroll
            for (int i = 0; i < 4; i++)
#pragma unroll
                for (int j = 0; j < 4; j++) acc[i][j] = ff2(am[i], bb[j], acc[i][j]);
        }
        __syncthreads();
    }
#pragma unroll
    for (int i = 0; i < 4; i++) {
        int mlo = m0 + ty * 8 + 2 * i;
        float blo = rowBias ? rowBias[(long)f * sBias + mlo] : 0.f;
        float bhi = rowBias ? rowBias[(long)f * sBias + mlo + 1] : 0.f;
        float2 c0 = unpk2(acc[i][0]), c1 = unpk2(acc[i][1]);
        float2 c2 = unpk2(acc[i][2]), c3 = unpk2(acc[i][3]);
        float4 vlo = {c0.x + blo, c1.x + blo, c2.x + blo, c3.x + blo};
        float4 vhi = {c0.y + bhi, c1.y + bhi, c2.y + bhi, c3.y + bhi};
        *(float4*)&C[(long)mlo * ldc + n0 + tx * 4] = vlo;
        *(float4*)&C[(long)(mlo + 1) * ldc + n0 + tx * 4] = vhi;
    }
}

// ---------------- per-row logsumexp + diagonal of log_softmax --------------
__global__ void k_lse() {
    int row = blockIdx.x;                       // f*512 + b
    const float* p = g_totals + (size_t)row * Bn;
    int tid = threadIdx.x;                      // 128
    __shared__ float sm[128];
    float mx = -1e30f;
    for (int c = tid; c < Bn; c += 128) mx = fmaxf(mx, p[c]);
    sm[tid] = mx; __syncthreads();
    for (int s = 64; s; s >>= 1) { if (tid < s) sm[tid] = fmaxf(sm[tid], sm[tid + s]); __syncthreads(); }
    mx = sm[0]; __syncthreads();
    float sum = 0.f;
    for (int c = tid; c < Bn; c += 128) sum += expf(p[c] - mx);
    sm[tid] = sum; __syncthreads();
    for (int s = 64; s; s >>= 1) { if (tid < s) sm[tid] += sm[tid + s]; __syncthreads(); }
    if (tid == 0) {
        float lse = mx + logf(sm[0]);
        int b = row & 511, f = row >> 9;
        g_diag[row] = p[b] - lse;
        if (f == Ff - 1) g_lse15[b] = lse;
    }
}

// ---------------- accuracy: argmax over b of softmax column ----------------
__global__ void k_acc() {
    int c = blockIdx.x;
    const float* p = g_totals + (size_t)(Ff - 1) * Bn * Bn;
    int tid = threadIdx.x;                      // 128
    float best = -1e30f; int bi = 1 << 30;
    for (int b = tid; b < Bn; b += 128) {
        float v = p[(size_t)b * Bn + c] - g_lse15[b];
        if (v > best) { best = v; bi = b; }
    }
    __shared__ float sv[128]; __shared__ int si[128];
    sv[tid] = best; si[tid] = bi; __syncthreads();
    for (int s = 64; s; s >>= 1) {
        if (tid < s) {
            float v2 = sv[tid + s]; int i2 = si[tid + s];
            if (v2 > sv[tid] || (v2 == sv[tid] && i2 < si[tid])) { sv[tid] = v2; si[tid] = i2; }
        }
        __syncthreads();
    }
    if (tid == 0) g_ok[c] = (si[0] == c) ? 1 : 0;
}

// ---------------- deterministic final reduction -----------------------------
__global__ void k_final(float* __restrict__ out) {
    __shared__ float s[256]; __shared__ int si[256];
    int tid = threadIdx.x;
    float sum = 0.f;
    for (int i = tid; i < Ff * Bn; i += 256) sum += g_diag[i];
    int cnt = 0;
    for (int i = tid; i < Bn; i += 256) cnt += g_ok[i];
    s[tid] = sum; si[tid] = cnt; __syncthreads();
    for (int st = 128; st; st >>= 1) {
        if (tid < st) { s[tid] += s[tid + st]; si[tid] += si[tid + st]; }
        __syncthreads();
    }
    if (tid == 0) {
        out[0] = (float)si[0] / (float)Bn;               // accuracy
        out[1] = -s[0] / (float)(Ff * Bn);               // nce
    }
}

// ---------------- host ----------------
extern "C" void kernel_launch(void* const* d_in, const int* in_sizes, int n_in,
                              void* d_out, int out_size) {
    const float* zqst   = (const float*)d_in[0];
    const float* zex    = (const float*)d_in[1];
    const float* zqx    = (const float*)d_in[2];
    const float* hidden = (const float*)d_in[3];
    const float* Wih = (const float*)d_in[4];
    const float* Whh = (const float*)d_in[5];
    const float* bih = (const float*)d_in[6];
    const float* bhh = (const float*)d_in[7];
    const float* Wkw = (const float*)d_in[8];
    const float* Wkb = (const float*)d_in[9];
    float* out = (float*)d_out;

    float *p_wkT, *p_ctT, *p_predT, *p_encT, *p_totals;
    cudaGetSymbolAddress((void**)&p_wkT,    g_WkT);
    cudaGetSymbolAddress((void**)&p_ctT,    g_ctT);
    cudaGetSymbolAddress((void**)&p_predT,  g_predT);
    cudaGetSymbolAddress((void**)&p_encT,   g_encT);
    cudaGetSymbolAddress((void**)&p_totals, g_totals);

    // launch order: k_gru is the 4th launch so ncu captures it next round
    k_transpose_wih<<<(Gg * Kd + 255) / 256, 256>>>(Wih);
    k_transpose_wk<<<(Ff * Kd * KH + 255) / 256, 256>>>(Wkw);

    // gx GEMM + full passthrough copy (float2 — dst is only 8B aligned)
    k_gx<<<dim3(GXB + CPB, Gg / 128), 256>>>(zqst, bih,
        (const float2*)zex, (const float2*)zqx, (float2*)(out + 2));

    // GRU v2 (warp-uniform halves, broadcast LDS)
    k_gru<<<Bn / 4, 768>>>(hidden, Whh, bhh);

    k_enc<<<(Ff * Kd * Bn + 255) / 256, 256>>>(zqst);

    // predT[f][k][c] = sum_h WkT[f][h][k] * ctT[h][c] + Wk_b[f][k]
    k_gemm<<<dim3(Bn / 128, Kd / 64, Ff), 256>>>(p_wkT, p_ctT, p_predT,
        Kd, Bn, Bn, KH, (long)KH * Kd, 0L, (long)Kd * Bn, Wkb, Kd);
    // totals[f][b][c] = sum_k encT[f][k][b] * predT[f][k][c]
    k_gemm<<<dim3(Bn / 128, Bn / 64, Ff), 256>>>(p_encT, p_predT, p_totals,
        Bn, Bn, Bn, Kd, (long)Kd * Bn, (long)Kd * Bn, (long)Bn * Bn, nullptr, 0);

    k_lse<<<Ff * Bn, 128>>>();
    k_acc<<<Bn, 128>>>();
    k_final<<<1, 256>>>(out);
}

// round 8
// speedup vs baseline: 1.5349x; 1.0232x over previous
#include <cuda_runtime.h>
#include <math.h>

// Problem constants (from setup_inputs; p_sample=100 fixed)
#define Bn   512
#define Kd   256
#define KH   128
#define Gg   384     // 3*KH
#define Tt   101     // p_sample+1
#define Ff   16
#define MGX  (Bn*Tt) // 51712 = 808*64 exactly
#define GXB  (MGX/64)  // 808 gemm blocks along m
#define GRUCP 20       // copy CTAs fused into k_gru (128+20 = 148 SMs)

// ---------------- packed fp32x2 helpers (sm_103a FFMA2) ----------------
typedef unsigned long long ull;
__device__ __forceinline__ ull ff2(ull a, ull b, ull c) {
    ull d;
    asm("fma.rn.f32x2 %0, %1, %2, %3;" : "=l"(d) : "l"(a), "l"(b), "l"(c));
    return d;
}
__device__ __forceinline__ ull dup2(float x) {
    ull r; asm("mov.b64 %0, {%1, %1};" : "=l"(r) : "f"(x)); return r;
}
__device__ __forceinline__ float2 unpk2(ull v) {
    float2 r; asm("mov.b64 {%0, %1}, %2;" : "=f"(r.x), "=f"(r.y) : "l"(v)); return r;
}
__device__ __forceinline__ float fast_sigmoid(float x) {
    return 1.f / (1.f + __expf(-x));
}
__device__ __forceinline__ float fast_tanh(float x) {
    float e = __expf(2.f * x);
    return 1.f - 2.f / (e + 1.f);
}

// ---------------- scratch (device globals: allocation-free) ----------------
__device__ __align__(16) float g_gx[MGX * Gg];          // [m=b*101+t][g]
__device__ __align__(16) float g_WihT[Kd * Gg];         // [k][g]
__device__ __align__(16) float g_WkT[Ff * KH * Kd];     // [f][h][k]
__device__ __align__(16) float g_ctT[KH * Bn];          // [h][b]
__device__ __align__(16) float g_predT[Ff * Kd * Bn];   // [f][k][c]
__device__ __align__(16) float g_encT[Ff * Kd * Bn];    // [f][k][b]
__device__ __align__(16) float g_totals[Ff * Bn * Bn];  // [f][b][c]
__device__ float g_lse15[Bn];
__device__ float g_diag[Ff * Bn];
__device__ int   g_ok[Bn];

// ---------------- weight transposes (tiny) ----------------
__global__ void k_transpose_wih(const float* __restrict__ W) {
    int idx = blockIdx.x * 256 + threadIdx.x;           // 384*256
    if (idx < Gg * Kd) {
        int g = idx / Kd, k = idx % Kd;
        g_WihT[k * Gg + g] = W[idx];
    }
}
__global__ void k_transpose_wk(const float* __restrict__ W) {
    int idx = blockIdx.x * 256 + threadIdx.x;           // 16*256*128
    if (idx < Ff * Kd * KH) {
        int f = idx >> 15, r = idx & 32767, k = r >> 7, h = r & 127;
        g_WkT[f * (KH * Kd) + h * Kd + k] = W[idx];
    }
}

// ---------------- encoded gather: encT[f][k][b] = z[b][k][101+f] -----------
__global__ void k_enc(const float* __restrict__ z) {
    int idx = blockIdx.x * 256 + threadIdx.x;    // 16*256*512
    if (idx < Ff * Kd * Bn) {
        int b = idx & 511, k = (idx >> 9) & 255, f = idx >> 17;
        g_encT[idx] = z[(size_t)b * (Kd * 256) + k * 256 + (Tt + f)];
    }
}

// ---------------- gx = seq @ W_ih^T + b_ih  (pure GEMM, no copy) -----------
__global__ __launch_bounds__(256) void k_gx(const float* __restrict__ z,
                                            const float* __restrict__ bih) {
    __shared__ __align__(16) float As[32][64];
    __shared__ __align__(16) float Bs[32][128];
    int tid = threadIdx.x;
    int m0 = blockIdx.x * 64, n0 = blockIdx.y * 128;

    int mA = m0 + (tid & 63);
    int kA0 = tid >> 6;                       // 0..3
    int bq = mA / Tt, tq = mA - bq * Tt;      // fixed per thread
    const float* aptr = z + (size_t)bq * (Kd * 256) + tq;

    int nB = n0 + (tid & 127);
    int kB0 = tid >> 7;                       // 0..1
    int tx = tid & 31, ty = tid >> 5;

    ull acc[4][4];                             // [m-pair][n], packed along m
#pragma unroll
    for (int i = 0; i < 4; i++)
#pragma unroll
        for (int j = 0; j < 4; j++) acc[i][j] = 0ULL;

    for (int kt = 0; kt < Kd; kt += 32) {
#pragma unroll
        for (int i = 0; i < 8; i++) {
            int kl = kA0 + 4 * i;
            As[kl][tid & 63] = aptr[(size_t)(kt + kl) * 256];
        }
#pragma unroll
        for (int i = 0; i < 16; i++) {
            int kl = kB0 + 2 * i;
            Bs[kl][tid & 127] = g_WihT[(kt + kl) * Gg + nB];
        }
        __syncthreads();
#pragma unroll
        for (int k = 0; k < 32; k++) {
            ulonglong2 a0 = *(const ulonglong2*)&As[k][ty * 8];
            ulonglong2 a1 = *(const ulonglong2*)&As[k][ty * 8 + 4];
            float4 b4 = *(const float4*)&Bs[k][tx * 4];
            ull bb[4] = {dup2(b4.x), dup2(b4.y), dup2(b4.z), dup2(b4.w)};
            ull am[4] = {a0.x, a0.y, a1.x, a1.y};
#pragma unroll
            for (int i = 0; i < 4; i++)
#pragma unroll
                for (int j = 0; j < 4; j++) acc[i][j] = ff2(am[i], bb[j], acc[i][j]);
        }
        __syncthreads();
    }
    float4 bias = *(const float4*)&bih[n0 + tx * 4];
#pragma unroll
    for (int i = 0; i < 4; i++) {
        float2 c0 = unpk2(acc[i][0]), c1 = unpk2(acc[i][1]);
        float2 c2 = unpk2(acc[i][2]), c3 = unpk2(acc[i][3]);
        int mlo = m0 + ty * 8 + 2 * i;
        float4 vlo = {c0.x + bias.x, c1.x + bias.y, c2.x + bias.z, c3.x + bias.w};
        float4 vhi = {c0.y + bias.x, c1.y + bias.y, c2.y + bias.z, c3.y + bias.w};
        *(float4*)&g_gx[(size_t)mlo * Gg + n0 + tx * 4] = vlo;
        *(float4*)&g_gx[(size_t)(mlo + 1) * Gg + n0 + tx * 4] = vhi;
    }
}

// ---------------- persistent GRU v2 + fused FULL passthrough copy ----------
// GRU CTAs: blockIdx.x < 128 (1 per SM: 768 thr x 80 regs).
// Copy CTAs: blockIdx.x in [128, 148) run on the 20 otherwise-idle SMs;
// GRU DRAM is 3.7%, so the copy's ~2TB/s demand is uncontended.
__global__ __launch_bounds__(768, 1) void k_gru(const float* __restrict__ h0,
                                                const float* __restrict__ Whh,
                                                const float* __restrict__ bhh,
                                                const float2* __restrict__ cpA,
                                                const float2* __restrict__ cpB,
                                                float2* __restrict__ cpDst) {
    if (blockIdx.x >= (Bn / 4)) {
        const long n2 = (long)Bn * Kd * 256 / 2;   // 16,777,216 float2 per tensor
        long i = (blockIdx.x - Bn / 4) * 768L + threadIdx.x;
        const long stride = (long)GRUCP * 768;
        for (; i < n2; i += stride) {
            cpDst[i]      = cpA[i];
            cpDst[i + n2] = cpB[i];
        }
        return;
    }

    __shared__ __align__(16) float h_sm[4][128];
    __shared__ float gh2[4][2][Gg];
    __shared__ float bh_sm[Gg];
    int tid = threadIdx.x;
    int b0 = blockIdx.x * 4;
    int half = (tid >= Gg) ? 1 : 0;
    int g = tid - half * Gg;

    // cache this thread's 64 W_hh weights as 32 packed fp32 pairs (64 regs)
    ull w2[32];
    {
        const ulonglong2* wp = (const ulonglong2*)(Whh + g * KH + half * 64);
#pragma unroll
        for (int i = 0; i < 16; i++) {
            ulonglong2 v = wp[i];
            w2[2 * i] = v.x; w2[2 * i + 1] = v.y;
        }
    }

    if (tid < Gg) bh_sm[tid] = bhh[tid];
    int r2 = tid >> 7, j2 = tid & 127;         // valid for tid<512
    if (tid < 512) h_sm[r2][j2] = h0[(b0 + r2) * KH + j2];
    __syncthreads();

    const float* gp0 = g_gx + (size_t)(b0 + r2) * Tt * Gg;
    for (int t = 0; t < Tt; t++) {
        // prefetch this step's gx (consumed in phase 2)
        float xr = 0.f, xz = 0.f, xn = 0.f;
        if (tid < 512) {
            const float* gp = gp0 + (size_t)t * Gg;
            xr = gp[j2]; xz = gp[128 + j2]; xn = gp[256 + j2];
        }
        // phase 1: partial dot for (row r, gate g, half) -- all LDS broadcast
#pragma unroll
        for (int r = 0; r < 4; r++) {
            ull accA = 0ULL, accB = 0ULL;
            const ulonglong2* hp = (const ulonglong2*)&h_sm[r][half * 64];
#pragma unroll
            for (int i = 0; i < 16; i++) {
                ulonglong2 hv = hp[i];           // warp-uniform address
                accA = ff2(w2[2 * i],     hv.x, accA);
                accB = ff2(w2[2 * i + 1], hv.y, accB);
            }
            float2 sa = unpk2(accA), sb = unpk2(accB);
            gh2[r][half][g] = (sa.x + sa.y) + (sb.x + sb.y);
        }
        __syncthreads();
        // phase 2: combine halves, gates + state update
        if (tid < 512) {
            float hr = gh2[r2][0][j2]       + gh2[r2][1][j2]       + bh_sm[j2];
            float hz = gh2[r2][0][128 + j2] + gh2[r2][1][128 + j2] + bh_sm[128 + j2];
            float hn = gh2[r2][0][256 + j2] + gh2[r2][1][256 + j2] + bh_sm[256 + j2];
            float rr = fast_sigmoid(xr + hr);
            float zz = fast_sigmoid(xz + hz);
            float nn = fast_tanh(xn + rr * hn);
            float hp = h_sm[r2][j2];
            h_sm[r2][j2] = (1.f - zz) * nn + zz * hp;
        }
        __syncthreads();
    }
    if (tid < 512) g_ctT[j2 * Bn + (b0 + r2)] = h_sm[r2][j2];
}

// ------------- generic batched GEMM (round-2 proven): C=sum_k A[k][m]B[k][n]
__global__ __launch_bounds__(256) void k_gemm(const float* __restrict__ A,
                                              const float* __restrict__ Bm,
                                              float* __restrict__ C,
                                              int lda, int ldb, int ldc, int KK,
                                              long sA, long sB, long sC,
                                              const float* __restrict__ rowBias, int sBias) {
    __shared__ __align__(16) float As[32][64];
    __shared__ __align__(16) float Bs[32][128];
    int f = blockIdx.z;
    A += (long)f * sA; Bm += (long)f * sB; C += (long)f * sC;
    int tid = threadIdx.x;
    int m0 = blockIdx.y * 64, n0 = blockIdx.x * 128;
    int mA = m0 + (tid & 63), kA0 = tid >> 6;
    int nB = n0 + (tid & 127), kB0 = tid >> 7;
    int tx = tid & 31, ty = tid >> 5;
    ull acc[4][4];
#pragma unroll
    for (int i = 0; i < 4; i++)
#pragma unroll
        for (int j = 0; j < 4; j++) acc[i][j] = 0ULL;

    for (int kt = 0; kt < KK; kt += 32) {
#pragma unroll
        for (int i = 0; i < 8; i++) { int kl = kA0 + 4 * i; As[kl][tid & 63] = A[(long)(kt + kl) * lda + mA]; }
#pragma unroll
        for (int i = 0; i < 16; i++) { int kl = kB0 + 2 * i; Bs[kl][tid & 127] = Bm[(long)(kt + kl) * ldb + nB]; }
        __syncthreads();
#pragma unroll
        for (int k = 0; k < 32; k++) {
            ulonglong2 a0 = *(const ulonglong2*)&As[k][ty * 8];
            ulonglong2 a1 = *(const ulonglong2*)&As[k][ty * 8 + 4];
            float4 b4 = *(const float4*)&Bs[k][tx * 4];
            ull bb[4] = {dup2(b4.x), dup2(b4.y), dup2(b4.z), dup2(b4.w)};
            ull am[4] = {a0.x, a0.y, a1.x, a1.y};
#pragma unroll
            for (int i = 0; i < 4; i++)
#pragma unroll
                for (int j = 0; j < 4; j++) acc[i][j] = ff2(am[i], bb[j], acc[i][j]);
        }
        __syncthreads();
    }
#pragma unroll
    for (int i = 0; i < 4; i++) {
        int mlo = m0 + ty * 8 + 2 * i;
        float blo = rowBias ? rowBias[(long)f * sBias + mlo] : 0.f;
        float bhi = rowBias ? rowBias[(long)f * sBias + mlo + 1] : 0.f;
        float2 c0 = unpk2(acc[i][0]), c1 = unpk2(acc[i][1]);
        float2 c2 = unpk2(acc[i][2]), c3 = unpk2(acc[i][3]);
        float4 vlo = {c0.x + blo, c1.x + blo, c2.x + blo, c3.x + blo};
        float4 vhi = {c0.y + bhi, c1.y + bhi, c2.y + bhi, c3.y + bhi};
        *(float4*)&C[(long)mlo * ldc + n0 + tx * 4] = vlo;
        *(float4*)&C[(long)(mlo + 1) * ldc + n0 + tx * 4] = vhi;
    }
}

// ---------------- per-row logsumexp + diagonal of log_softmax --------------
__global__ void k_lse() {
    int row = blockIdx.x;                       // f*512 + b
    const float* p = g_totals + (size_t)row * Bn;
    int tid = threadIdx.x;                      // 128
    __shared__ float sm[128];
    float mx = -1e30f;
    for (int c = tid; c < Bn; c += 128) mx = fmaxf(mx, p[c]);
    sm[tid] = mx; __syncthreads();
    for (int s = 64; s; s >>= 1) { if (tid < s) sm[tid] = fmaxf(sm[tid], sm[tid + s]); __syncthreads(); }
    mx = sm[0]; __syncthreads();
    float sum = 0.f;
    for (int c = tid; c < Bn; c += 128) sum += expf(p[c] - mx);
    sm[tid] = sum; __syncthreads();
    for (int s = 64; s; s >>= 1) { if (tid < s) sm[tid] += sm[tid + s]; __syncthreads(); }
    if (tid == 0) {
        float lse = mx + logf(sm[0]);
        int b = row & 511, f = row >> 9;
        g_diag[row] = p[b] - lse;
        if (f == Ff - 1) g_lse15[b] = lse;
    }
}

// ---------------- accuracy: argmax over b of softmax column ----------------
__global__ void k_acc() {
    int c = blockIdx.x;
    const float* p = g_totals + (size_t)(Ff - 1) * Bn * Bn;
    int tid = threadIdx.x;                      // 128
    float best = -1e30f; int bi = 1 << 30;
    for (int b = tid; b < Bn; b += 128) {
        float v = p[(size_t)b * Bn + c] - g_lse15[b];
        if (v > best) { best = v; bi = b; }
    }
    __shared__ float sv[128]; __shared__ int si[128];
    sv[tid] = best; si[tid] = bi; __syncthreads();
    for (int s = 64; s; s >>= 1) {
        if (tid < s) {
            float v2 = sv[tid + s]; int i2 = si[tid + s];
            if (v2 > sv[tid] || (v2 == sv[tid] && i2 < si[tid])) { sv[tid] = v2; si[tid] = i2; }
        }
        __syncthreads();
    }
    if (tid == 0) g_ok[c] = (si[0] == c) ? 1 : 0;
}

// ---------------- deterministic final reduction -----------------------------
__global__ void k_final(float* __restrict__ out) {
    __shared__ float s[256]; __shared__ int si[256];
    int tid = threadIdx.x;
    float sum = 0.f;
    for (int i = tid; i < Ff * Bn; i += 256) sum += g_diag[i];
    int cnt = 0;
    for (int i = tid; i < Bn; i += 256) cnt += g_ok[i];
    s[tid] = sum; si[tid] = cnt; __syncthreads();
    for (int st = 128; st; st >>= 1) {
        if (tid < st) { s[tid] += s[tid + st]; si[tid] += si[tid + st]; }
        __syncthreads();
    }
    if (tid == 0) {
        out[0] = (float)si[0] / (float)Bn;               // accuracy
        out[1] = -s[0] / (float)(Ff * Bn);               // nce
    }
}

// ---------------- host ----------------
extern "C" void kernel_launch(void* const* d_in, const int* in_sizes, int n_in,
                              void* d_out, int out_size) {
    const float* zqst   = (const float*)d_in[0];
    const float* zex    = (const float*)d_in[1];
    const float* zqx    = (const float*)d_in[2];
    const float* hidden = (const float*)d_in[3];
    const float* Wih = (const float*)d_in[4];
    const float* Whh = (const float*)d_in[5];
    const float* bih = (const float*)d_in[6];
    const float* bhh = (const float*)d_in[7];
    const float* Wkw = (const float*)d_in[8];
    const float* Wkb = (const float*)d_in[9];
    float* out = (float*)d_out;

    float *p_wkT, *p_ctT, *p_predT, *p_encT, *p_totals;
    cudaGetSymbolAddress((void**)&p_wkT,    g_WkT);
    cudaGetSymbolAddress((void**)&p_ctT,    g_ctT);
    cudaGetSymbolAddress((void**)&p_predT,  g_predT);
    cudaGetSymbolAddress((void**)&p_encT,   g_encT);
    cudaGetSymbolAddress((void**)&p_totals, g_totals);

    // launch order keeps k_gru as the 4th launch (ncu captures it)
    k_transpose_wih<<<(Gg * Kd + 255) / 256, 256>>>(Wih);
    k_transpose_wk<<<(Ff * Kd * KH + 255) / 256, 256>>>(Wkw);

    // gx GEMM (pure)
    k_gx<<<dim3(GXB, Gg / 128), 256>>>(zqst, bih);

    // GRU v2 + full passthrough copy on the 20 idle SMs
    k_gru<<<Bn / 4 + GRUCP, 768>>>(hidden, Whh, bhh,
        (const float2*)zex, (const float2*)zqx, (float2*)(out + 2));

    k_enc<<<(Ff * Kd * Bn + 255) / 256, 256>>>(zqst);

    // predT[f][k][c] = sum_h WkT[f][h][k] * ctT[h][c] + Wk_b[f][k]
    k_gemm<<<dim3(Bn / 128, Kd / 64, Ff), 256>>>(p_wkT, p_ctT, p_predT,
        Kd, Bn, Bn, KH, (long)KH * Kd, 0L, (long)Kd * Bn, Wkb, Kd);
    // totals[f][b][c] = sum_k encT[f][k][b] * predT[f][k][c]
    k_gemm<<<dim3(Bn / 128, Bn / 64, Ff), 256>>>(p_encT, p_predT, p_totals,
        Bn, Bn, Bn, Kd, (long)Kd * Bn, (long)Kd * Bn, (long)Bn * Bn, nullptr, 0);

    k_lse<<<Ff * Bn, 128>>>();
    k_acc<<<Bn, 128>>>();
    k_final<<<1, 256>>>(out);
}

// round 9
// speedup vs baseline: 1.5853x; 1.0329x over previous
#include <cuda_runtime.h>
#include <math.h>

// Problem constants (from setup_inputs; p_sample=100 fixed)
#define Bn   512
#define Kd   256
#define KH   128
#define Gg   384     // 3*KH
#define Tt   101     // p_sample+1
#define Ff   16
#define MGX  (Bn*Tt) // 51712 = 808*64 exactly
#define GXB  (MGX/64)  // 808 gemm blocks along m
#define CPB  256       // copy CTAs fused into k_gx (second half of copy)
#define GRUCP 20       // copy CTAs fused into k_gru (first half of copy)
#define N4   ((long)Bn * Kd * 256 / 4)   // float4 count per passthrough tensor

// ---------------- packed fp32x2 helpers (sm_103a FFMA2) ----------------
typedef unsigned long long ull;
__device__ __forceinline__ ull ff2(ull a, ull b, ull c) {
    ull d;
    asm("fma.rn.f32x2 %0, %1, %2, %3;" : "=l"(d) : "l"(a), "l"(b), "l"(c));
    return d;
}
__device__ __forceinline__ ull dup2(float x) {
    ull r; asm("mov.b64 %0, {%1, %1};" : "=l"(r) : "f"(x)); return r;
}
__device__ __forceinline__ float2 unpk2(ull v) {
    float2 r; asm("mov.b64 {%0, %1}, %2;" : "=f"(r.x), "=f"(r.y) : "l"(v)); return r;
}
__device__ __forceinline__ float fast_sigmoid(float x) {
    return 1.f / (1.f + __expf(-x));
}
__device__ __forceinline__ float fast_tanh(float x) {
    float e = __expf(2.f * x);
    return 1.f - 2.f / (e + 1.f);
}

// copy float4-sourced range [j0, j1) of both tensors; dst is float2 (8B aligned)
__device__ __forceinline__ void copy_range(const float4* __restrict__ a4,
                                           const float4* __restrict__ b4,
                                           float2* __restrict__ dst,
                                           long j0, long j1, long step) {
    const long o2 = 2 * N4;                   // float2 offset of second tensor
    for (long j = j0; j < j1; j += step) {
        float4 v = __ldg(&a4[j]);
        dst[2 * j]     = make_float2(v.x, v.y);
        dst[2 * j + 1] = make_float2(v.z, v.w);
        float4 w = __ldg(&b4[j]);
        dst[o2 + 2 * j]     = make_float2(w.x, w.y);
        dst[o2 + 2 * j + 1] = make_float2(w.z, w.w);
    }
}

// ---------------- scratch (device globals: allocation-free) ----------------
__device__ __align__(16) float g_gx[MGX * Gg];          // [m=b*101+t][g]
__device__ __align__(16) float g_WihT[Kd * Gg];         // [k][g]
__device__ __align__(16) float g_WkT[Ff * KH * Kd];     // [f][h][k]
__device__ __align__(16) float g_ctT[KH * Bn];          // [h][b]
__device__ __align__(16) float g_predT[Ff * Kd * Bn];   // [f][k][c]
__device__ __align__(16) float g_encT[Ff * Kd * Bn];    // [f][k][b]
__device__ __align__(16) float g_totals[Ff * Bn * Bn];  // [f][b][c]
__device__ float g_lse15[Bn];
__device__ float g_diag[Ff * Bn];
__device__ int   g_ok[Bn];

// ---------------- weight transposes (tiny) ----------------
__global__ void k_transpose_wih(const float* __restrict__ W) {
    int idx = blockIdx.x * 256 + threadIdx.x;           // 384*256
    if (idx < Gg * Kd) {
        int g = idx / Kd, k = idx % Kd;
        g_WihT[k * Gg + g] = W[idx];
    }
}
__global__ void k_transpose_wk(const float* __restrict__ W) {
    int idx = blockIdx.x * 256 + threadIdx.x;           // 16*256*128
    if (idx < Ff * Kd * KH) {
        int f = idx >> 15, r = idx & 32767, k = r >> 7, h = r & 127;
        g_WkT[f * (KH * Kd) + h * Kd + k] = W[idx];
    }
}

// ---------------- encoded gather: encT[f][k][b] = z[b][k][101+f] -----------
__global__ void k_enc(const float* __restrict__ z) {
    int idx = blockIdx.x * 256 + threadIdx.x;    // 16*256*512
    if (idx < Ff * Kd * Bn) {
        int b = idx & 511, k = (idx >> 9) & 255, f = idx >> 17;
        g_encT[idx] = z[(size_t)b * (Kd * 256) + k * 256 + (Tt + f)];
    }
}

// ---------------- gx = seq @ W_ih^T + b_ih  + second half of copy ----------
__global__ __launch_bounds__(256) void k_gx(const float* __restrict__ z,
                                            const float* __restrict__ bih,
                                            const float4* __restrict__ cpA,
                                            const float4* __restrict__ cpB,
                                            float2* __restrict__ cpDst) {
    if (blockIdx.x >= GXB) {
        if (blockIdx.y != 0) return;
        long j0 = N4 / 2 + (blockIdx.x - GXB) * 256L + threadIdx.x;
        copy_range(cpA, cpB, cpDst, j0, N4, (long)CPB * 256);
        return;
    }

    __shared__ __align__(16) float As[32][64];
    __shared__ __align__(16) float Bs[32][128];
    int tid = threadIdx.x;
    int m0 = blockIdx.x * 64, n0 = blockIdx.y * 128;

    int mA = m0 + (tid & 63);
    int kA0 = tid >> 6;                       // 0..3
    int bq = mA / Tt, tq = mA - bq * Tt;      // fixed per thread
    const float* aptr = z + (size_t)bq * (Kd * 256) + tq;

    int nB = n0 + (tid & 127);
    int kB0 = tid >> 7;                       // 0..1
    int tx = tid & 31, ty = tid >> 5;

    ull acc[4][4];                             // [m-pair][n], packed along m
#pragma unroll
    for (int i = 0; i < 4; i++)
#pragma unroll
        for (int j = 0; j < 4; j++) acc[i][j] = 0ULL;

    for (int kt = 0; kt < Kd; kt += 32) {
#pragma unroll
        for (int i = 0; i < 8; i++) {
            int kl = kA0 + 4 * i;
            As[kl][tid & 63] = aptr[(size_t)(kt + kl) * 256];
        }
#pragma unroll
        for (int i = 0; i < 16; i++) {
            int kl = kB0 + 2 * i;
            Bs[kl][tid & 127] = g_WihT[(kt + kl) * Gg + nB];
        }
        __syncthreads();
#pragma unroll
        for (int k = 0; k < 32; k++) {
            ulonglong2 a0 = *(const ulonglong2*)&As[k][ty * 8];
            ulonglong2 a1 = *(const ulonglong2*)&As[k][ty * 8 + 4];
            float4 b4 = *(const float4*)&Bs[k][tx * 4];
            ull bb[4] = {dup2(b4.x), dup2(b4.y), dup2(b4.z), dup2(b4.w)};
            ull am[4] = {a0.x, a0.y, a1.x, a1.y};
#pragma unroll
            for (int i = 0; i < 4; i++)
#pragma unroll
                for (int j = 0; j < 4; j++) acc[i][j] = ff2(am[i], bb[j], acc[i][j]);
        }
        __syncthreads();
    }
    float4 bias = *(const float4*)&bih[n0 + tx * 4];
#pragma unroll
    for (int i = 0; i < 4; i++) {
        float2 c0 = unpk2(acc[i][0]), c1 = unpk2(acc[i][1]);
        float2 c2 = unpk2(acc[i][2]), c3 = unpk2(acc[i][3]);
        int mlo = m0 + ty * 8 + 2 * i;
        float4 vlo = {c0.x + bias.x, c1.x + bias.y, c2.x + bias.z, c3.x + bias.w};
        float4 vhi = {c0.y + bias.x, c1.y + bias.y, c2.y + bias.z, c3.y + bias.w};
        *(float4*)&g_gx[(size_t)mlo * Gg + n0 + tx * 4] = vlo;
        *(float4*)&g_gx[(size_t)(mlo + 1) * Gg + n0 + tx * 4] = vhi;
    }
}

// ---------------- persistent GRU v2 + first half of copy -------------------
__global__ __launch_bounds__(768, 1) void k_gru(const float* __restrict__ h0,
                                                const float* __restrict__ Whh,
                                                const float* __restrict__ bhh,
                                                const float4* __restrict__ cpA,
                                                const float4* __restrict__ cpB,
                                                float2* __restrict__ cpDst) {
    if (blockIdx.x >= (Bn / 4)) {
        long j0 = (blockIdx.x - Bn / 4) * 768L + threadIdx.x;
        copy_range(cpA, cpB, cpDst, j0, N4 / 2, (long)GRUCP * 768);
        return;
    }

    __shared__ __align__(16) float h_sm[4][128];
    __shared__ float gh2[4][2][Gg];
    __shared__ float bh_sm[Gg];
    int tid = threadIdx.x;
    int b0 = blockIdx.x * 4;
    int half = (tid >= Gg) ? 1 : 0;
    int g = tid - half * Gg;

    // cache this thread's 64 W_hh weights as 32 packed fp32 pairs (64 regs)
    ull w2[32];
    {
        const ulonglong2* wp = (const ulonglong2*)(Whh + g * KH + half * 64);
#pragma unroll
        for (int i = 0; i < 16; i++) {
            ulonglong2 v = wp[i];
            w2[2 * i] = v.x; w2[2 * i + 1] = v.y;
        }
    }

    if (tid < Gg) bh_sm[tid] = bhh[tid];
    int r2 = tid >> 7, j2 = tid & 127;         // valid for tid<512
    if (tid < 512) h_sm[r2][j2] = h0[(b0 + r2) * KH + j2];
    __syncthreads();

    const float* gp0 = g_gx + (size_t)(b0 + r2) * Tt * Gg;
    for (int t = 0; t < Tt; t++) {
        // prefetch this step's gx (consumed in phase 2)
        float xr = 0.f, xz = 0.f, xn = 0.f;
        if (tid < 512) {
            const float* gp = gp0 + (size_t)t * Gg;
            xr = gp[j2]; xz = gp[128 + j2]; xn = gp[256 + j2];
        }
        // phase 1: partial dot for (row r, gate g, half) -- all LDS broadcast
#pragma unroll
        for (int r = 0; r < 4; r++) {
            ull accA = 0ULL, accB = 0ULL;
            const ulonglong2* hp = (const ulonglong2*)&h_sm[r][half * 64];
#pragma unroll
            for (int i = 0; i < 16; i++) {
                ulonglong2 hv = hp[i];           // warp-uniform address
                accA = ff2(w2[2 * i],     hv.x, accA);
                accB = ff2(w2[2 * i + 1], hv.y, accB);
            }
            float2 sa = unpk2(accA), sb = unpk2(accB);
            gh2[r][half][g] = (sa.x + sa.y) + (sb.x + sb.y);
        }
        __syncthreads();
        // phase 2: combine halves, gates + state update
        if (tid < 512) {
            float hr = gh2[r2][0][j2]       + gh2[r2][1][j2]       + bh_sm[j2];
            float hz = gh2[r2][0][128 + j2] + gh2[r2][1][128 + j2] + bh_sm[128 + j2];
            float hn = gh2[r2][0][256 + j2] + gh2[r2][1][256 + j2] + bh_sm[256 + j2];
            float rr = fast_sigmoid(xr + hr);
            float zz = fast_sigmoid(xz + hz);
            float nn = fast_tanh(xn + rr * hn);
            float hp = h_sm[r2][j2];
            h_sm[r2][j2] = (1.f - zz) * nn + zz * hp;
        }
        __syncthreads();
    }
    if (tid < 512) g_ctT[j2 * Bn + (b0 + r2)] = h_sm[r2][j2];
}

// ------------- generic batched GEMM (round-2 proven): C=sum_k A[k][m]B[k][n]
__global__ __launch_bounds__(256) void k_gemm(const float* __restrict__ A,
                                              const float* __restrict__ Bm,
                                              float* __restrict__ C,
                                              int lda, int ldb, int ldc, int KK,
                                              long sA, long sB, long sC,
                                              const float* __restrict__ rowBias, int sBias) {
    __shared__ __align__(16) float As[32][64];
    __shared__ __align__(16) float Bs[32][128];
    int f = blockIdx.z;
    A += (long)f * sA; Bm += (long)f * sB; C += (long)f * sC;
    int tid = threadIdx.x;
    int m0 = blockIdx.y * 64, n0 = blockIdx.x * 128;
    int mA = m0 + (tid & 63), kA0 = tid >> 6;
    int nB = n0 + (tid & 127), kB0 = tid >> 7;
    int tx = tid & 31, ty = tid >> 5;
    ull acc[4][4];
#pragma unroll
    for (int i = 0; i < 4; i++)
#pragma unroll
        for (int j = 0; j < 4; j++) acc[i][j] = 0ULL;

    for (int kt = 0; kt < KK; kt += 32) {
#pragma unroll
        for (int i = 0; i < 8; i++) { int kl = kA0 + 4 * i; As[kl][tid & 63] = A[(long)(kt + kl) * lda + mA]; }
#pragma unroll
        for (int i = 0; i < 16; i++) { int kl = kB0 + 2 * i; Bs[kl][tid & 127] = Bm[(long)(kt + kl) * ldb + nB]; }
        __syncthreads();
#pragma unroll
        for (int k = 0; k < 32; k++) {
            ulonglong2 a0 = *(const ulonglong2*)&As[k][ty * 8];
            ulonglong2 a1 = *(const ulonglong2*)&As[k][ty * 8 + 4];
            float4 b4 = *(const float4*)&Bs[k][tx * 4];
            ull bb[4] = {dup2(b4.x), dup2(b4.y), dup2(b4.z), dup2(b4.w)};
            ull am[4] = {a0.x, a0.y, a1.x, a1.y};
#pragma unroll
            for (int i = 0; i < 4; i++)
#pragma unroll
                for (int j = 0; j < 4; j++) acc[i][j] = ff2(am[i], bb[j], acc[i][j]);
        }
        __syncthreads();
    }
#pragma unroll
    for (int i = 0; i < 4; i++) {
        int mlo = m0 + ty * 8 + 2 * i;
        float blo = rowBias ? rowBias[(long)f * sBias + mlo] : 0.f;
        float bhi = rowBias ? rowBias[(long)f * sBias + mlo + 1] : 0.f;
        float2 c0 = unpk2(acc[i][0]), c1 = unpk2(acc[i][1]);
        float2 c2 = unpk2(acc[i][2]), c3 = unpk2(acc[i][3]);
        float4 vlo = {c0.x + blo, c1.x + blo, c2.x + blo, c3.x + blo};
        float4 vhi = {c0.y + bhi, c1.y + bhi, c2.y + bhi, c3.y + bhi};
        *(float4*)&C[(long)mlo * ldc + n0 + tx * 4] = vlo;
        *(float4*)&C[(long)(mlo + 1) * ldc + n0 + tx * 4] = vhi;
    }
}

// ---------------- per-row logsumexp + diagonal of log_softmax --------------
__global__ void k_lse() {
    int row = blockIdx.x;                       // f*512 + b
    const float* p = g_totals + (size_t)row * Bn;
    int tid = threadIdx.x;                      // 128
    __shared__ float sm[128];
    float mx = -1e30f;
    for (int c = tid; c < Bn; c += 128) mx = fmaxf(mx, p[c]);
    sm[tid] = mx; __syncthreads();
    for (int s = 64; s; s >>= 1) { if (tid < s) sm[tid] = fmaxf(sm[tid], sm[tid + s]); __syncthreads(); }
    mx = sm[0]; __syncthreads();
    float sum = 0.f;
    for (int c = tid; c < Bn; c += 128) sum += expf(p[c] - mx);
    sm[tid] = sum; __syncthreads();
    for (int s = 64; s; s >>= 1) { if (tid < s) sm[tid] += sm[tid + s]; __syncthreads(); }
    if (tid == 0) {
        float lse = mx + logf(sm[0]);
        int b = row & 511, f = row >> 9;
        g_diag[row] = p[b] - lse;
        if (f == Ff - 1) g_lse15[b] = lse;
    }
}

// ---------------- accuracy: argmax over b of softmax column ----------------
__global__ void k_acc() {
    int c = blockIdx.x;
    const float* p = g_totals + (size_t)(Ff - 1) * Bn * Bn;
    int tid = threadIdx.x;                      // 128
    float best = -1e30f; int bi = 1 << 30;
    for (int b = tid; b < Bn; b += 128) {
        float v = p[(size_t)b * Bn + c] - g_lse15[b];
        if (v > best) { best = v; bi = b; }
    }
    __shared__ float sv[128]; __shared__ int si[128];
    sv[tid] = best; si[tid] = bi; __syncthreads();
    for (int s = 64; s; s >>= 1) {
        if (tid < s) {
            float v2 = sv[tid + s]; int i2 = si[tid + s];
            if (v2 > sv[tid] || (v2 == sv[tid] && i2 < si[tid])) { sv[tid] = v2; si[tid] = i2; }
        }
        __syncthreads();
    }
    if (tid == 0) g_ok[c] = (si[0] == c) ? 1 : 0;
}

// ---------------- deterministic final reduction -----------------------------
__global__ void k_final(float* __restrict__ out) {
    __shared__ float s[256]; __shared__ int si[256];
    int tid = threadIdx.x;
    float sum = 0.f;
    for (int i = tid; i < Ff * Bn; i += 256) sum += g_diag[i];
    int cnt = 0;
    for (int i = tid; i < Bn; i += 256) cnt += g_ok[i];
    s[tid] = sum; si[tid] = cnt; __syncthreads();
    for (int st = 128; st; st >>= 1) {
        if (tid < st) { s[tid] += s[tid + st]; si[tid] += si[tid + st]; }
        __syncthreads();
    }
    if (tid == 0) {
        out[0] = (float)si[0] / (float)Bn;               // accuracy
        out[1] = -s[0] / (float)(Ff * Bn);               // nce
    }
}

// ---------------- host ----------------
extern "C" void kernel_launch(void* const* d_in, const int* in_sizes, int n_in,
                              void* d_out, int out_size) {
    const float* zqst   = (const float*)d_in[0];
    const float* zex    = (const float*)d_in[1];
    const float* zqx    = (const float*)d_in[2];
    const float* hidden = (const float*)d_in[3];
    const float* Wih = (const float*)d_in[4];
    const float* Whh = (const float*)d_in[5];
    const float* bih = (const float*)d_in[6];
    const float* bhh = (const float*)d_in[7];
    const float* Wkw = (const float*)d_in[8];
    const float* Wkb = (const float*)d_in[9];
    float* out = (float*)d_out;

    float *p_wkT, *p_ctT, *p_predT, *p_encT, *p_totals;
    cudaGetSymbolAddress((void**)&p_wkT,    g_WkT);
    cudaGetSymbolAddress((void**)&p_ctT,    g_ctT);
    cudaGetSymbolAddress((void**)&p_predT,  g_predT);
    cudaGetSymbolAddress((void**)&p_encT,   g_encT);
    cudaGetSymbolAddress((void**)&p_totals, g_totals);

    // launch order keeps k_gru as the 4th launch (ncu captures it)
    k_transpose_wih<<<(Gg * Kd + 255) / 256, 256>>>(Wih);
    k_transpose_wk<<<(Ff * Kd * KH + 255) / 256, 256>>>(Wkw);

    // gx GEMM + second half of passthrough copy
    k_gx<<<dim3(GXB + CPB, Gg / 128), 256>>>(zqst, bih,
        (const float4*)zex, (const float4*)zqx, (float2*)(out + 2));

    // GRU v2 + first half of passthrough copy on the 20 idle SMs
    k_gru<<<Bn / 4 + GRUCP, 768>>>(hidden, Whh, bhh,
        (const float4*)zex, (const float4*)zqx, (float2*)(out + 2));

    k_enc<<<(Ff * Kd * Bn + 255) / 256, 256>>>(zqst);

    // predT[f][k][c] = sum_h WkT[f][h][k] * ctT[h][c] + Wk_b[f][k]
    k_gemm<<<dim3(Bn / 128, Kd / 64, Ff), 256>>>(p_wkT, p_ctT, p_predT,
        Kd, Bn, Bn, KH, (long)KH * Kd, 0L, (long)Kd * Bn, Wkb, Kd);
    // totals[f][b][c] = sum_k encT[f][k][b] * predT[f][k][c]
    k_gemm<<<dim3(Bn / 128, Bn / 64, Ff), 256>>>(p_encT, p_predT, p_totals,
        Bn, Bn, Bn, Kd, (long)Kd * Bn, (long)Kd * Bn, (long)Bn * Bn, nullptr, 0);

    k_lse<<<Ff * Bn, 128>>>();
    k_acc<<<Bn, 128>>>();
    k_final<<<1, 256>>>(out);
}

// round 10
// speedup vs baseline: 1.6702x; 1.0535x over previous
#include <cuda_runtime.h>
#include <math.h>

// Problem constants (from setup_inputs; p_sample=100 fixed)
#define Bn   512
#define Kd   256
#define KH   128
#define Gg   384     // 3*KH
#define Tt   101     // p_sample+1
#define Ff   16
#define MGX  (Bn*Tt) // 51712 = 808*64 exactly
#define GXB  (MGX/64)  // 808 gemm blocks along m
#define CPB  256       // extra x-blocks on k_gx (y0: copy, y1: enc)
#define GRUCP 20       // copy CTAs fused into k_gru (first half of copy)
#define N4   ((long)Bn * Kd * 256 / 4)   // float4 count per passthrough tensor

// ---------------- packed fp32x2 helpers (sm_103a FFMA2) ----------------
typedef unsigned long long ull;
__device__ __forceinline__ ull ff2(ull a, ull b, ull c) {
    ull d;
    asm("fma.rn.f32x2 %0, %1, %2, %3;" : "=l"(d) : "l"(a), "l"(b), "l"(c));
    return d;
}
__device__ __forceinline__ ull dup2(float x) {
    ull r; asm("mov.b64 %0, {%1, %1};" : "=l"(r) : "f"(x)); return r;
}
__device__ __forceinline__ float2 unpk2(ull v) {
    float2 r; asm("mov.b64 {%0, %1}, %2;" : "=f"(r.x), "=f"(r.y) : "l"(v)); return r;
}
__device__ __forceinline__ float fast_sigmoid(float x) {
    return 1.f / (1.f + __expf(-x));
}
__device__ __forceinline__ float fast_tanh(float x) {
    float e = __expf(2.f * x);
    return 1.f - 2.f / (e + 1.f);
}

// copy float4-sourced range [j0, j1) of both tensors; dst is float2 (8B aligned)
__device__ __forceinline__ void copy_range(const float4* __restrict__ a4,
                                           const float4* __restrict__ b4,
                                           float2* __restrict__ dst,
                                           long j0, long j1, long step) {
    const long o2 = 2 * N4;                   // float2 offset of second tensor
    for (long j = j0; j < j1; j += step) {
        float4 v = __ldg(&a4[j]);
        dst[2 * j]     = make_float2(v.x, v.y);
        dst[2 * j + 1] = make_float2(v.z, v.w);
        float4 w = __ldg(&b4[j]);
        dst[o2 + 2 * j]     = make_float2(w.x, w.y);
        dst[o2 + 2 * j + 1] = make_float2(w.z, w.w);
    }
}

// ---------------- scratch (device globals: allocation-free) ----------------
__device__ __align__(16) float g_gx[MGX * Gg];          // [m=b*101+t][g]
__device__ __align__(16) float g_WihT[Kd * Gg];         // [k][g]
__device__ __align__(16) float g_WkT[Ff * KH * Kd];     // [f][h][k]
__device__ __align__(16) float g_ctT[KH * Bn];          // [h][b]
__device__ __align__(16) float g_predT[Ff * Kd * Bn];   // [f][k][c]
__device__ __align__(16) float g_encT[Ff * Kd * Bn];    // [f][k][b]
__device__ __align__(16) float g_totals[Ff * Bn * Bn];  // [f][b][c]
__device__ float g_lse15[Bn];
__device__ float g_diag[Ff * Bn];
__device__ int   g_ok[Bn];

// ---------------- weight transposes (tiny) ----------------
__global__ void k_transpose_wih(const float* __restrict__ W) {
    int idx = blockIdx.x * 256 + threadIdx.x;           // 384*256
    if (idx < Gg * Kd) {
        int g = idx / Kd, k = idx % Kd;
        g_WihT[k * Gg + g] = W[idx];
    }
}
__global__ void k_transpose_wk(const float* __restrict__ W) {
    int idx = blockIdx.x * 256 + threadIdx.x;           // 16*256*128
    if (idx < Ff * Kd * KH) {
        int f = idx >> 15, r = idx & 32767, k = r >> 7, h = r & 127;
        g_WkT[f * (KH * Kd) + h * Kd + k] = W[idx];
    }
}

// ---------------- gx GEMM + fused copy (y0) + fused enc gather (y1) --------
__global__ __launch_bounds__(256) void k_gx(const float* __restrict__ z,
                                            const float* __restrict__ bih,
                                            const float4* __restrict__ cpA,
                                            const float4* __restrict__ cpB,
                                            float2* __restrict__ cpDst) {
    if (blockIdx.x >= GXB) {
        if (blockIdx.y == 0) {
            // second half of passthrough copy
            long j0 = N4 / 2 + (blockIdx.x - GXB) * 256L + threadIdx.x;
            copy_range(cpA, cpB, cpDst, j0, N4, (long)CPB * 256);
        } else if (blockIdx.y == 1) {
            // encoded gather: encT[f][k][b] = z[b][k][101+f]
            for (int idx = (blockIdx.x - GXB) * 256 + threadIdx.x;
                 idx < Ff * Kd * Bn; idx += CPB * 256) {
                int b = idx & 511, k = (idx >> 9) & 255, f = idx >> 17;
                g_encT[idx] = z[(size_t)b * (Kd * 256) + k * 256 + (Tt + f)];
            }
        }
        return;
    }

    __shared__ __align__(16) float As[32][64];
    __shared__ __align__(16) float Bs[32][128];
    int tid = threadIdx.x;
    int m0 = blockIdx.x * 64, n0 = blockIdx.y * 128;

    int mA = m0 + (tid & 63);
    int kA0 = tid >> 6;                       // 0..3
    int bq = mA / Tt, tq = mA - bq * Tt;      // fixed per thread
    const float* aptr = z + (size_t)bq * (Kd * 256) + tq;

    int nB = n0 + (tid & 127);
    int kB0 = tid >> 7;                       // 0..1
    int tx = tid & 31, ty = tid >> 5;

    ull acc[4][4];                             // [m-pair][n], packed along m
#pragma unroll
    for (int i = 0; i < 4; i++)
#pragma unroll
        for (int j = 0; j < 4; j++) acc[i][j] = 0ULL;

    for (int kt = 0; kt < Kd; kt += 32) {
#pragma unroll
        for (int i = 0; i < 8; i++) {
            int kl = kA0 + 4 * i;
            As[kl][tid & 63] = aptr[(size_t)(kt + kl) * 256];
        }
#pragma unroll
        for (int i = 0; i < 16; i++) {
            int kl = kB0 + 2 * i;
            Bs[kl][tid & 127] = g_WihT[(kt + kl) * Gg + nB];
        }
        __syncthreads();
#pragma unroll
        for (int k = 0; k < 32; k++) {
            ulonglong2 a0 = *(const ulonglong2*)&As[k][ty * 8];
            ulonglong2 a1 = *(const ulonglong2*)&As[k][ty * 8 + 4];
            float4 b4 = *(const float4*)&Bs[k][tx * 4];
            ull bb[4] = {dup2(b4.x), dup2(b4.y), dup2(b4.z), dup2(b4.w)};
            ull am[4] = {a0.x, a0.y, a1.x, a1.y};
#pragma unroll
            for (int i = 0; i < 4; i++)
#pragma unroll
                for (int j = 0; j < 4; j++) acc[i][j] = ff2(am[i], bb[j], acc[i][j]);
        }
        __syncthreads();
    }
    float4 bias = *(const float4*)&bih[n0 + tx * 4];
#pragma unroll
    for (int i = 0; i < 4; i++) {
        float2 c0 = unpk2(acc[i][0]), c1 = unpk2(acc[i][1]);
        float2 c2 = unpk2(acc[i][2]), c3 = unpk2(acc[i][3]);
        int mlo = m0 + ty * 8 + 2 * i;
        float4 vlo = {c0.x + bias.x, c1.x + bias.y, c2.x + bias.z, c3.x + bias.w};
        float4 vhi = {c0.y + bias.x, c1.y + bias.y, c2.y + bias.z, c3.y + bias.w};
        *(float4*)&g_gx[(size_t)mlo * Gg + n0 + tx * 4] = vlo;
        *(float4*)&g_gx[(size_t)(mlo + 1) * Gg + n0 + tx * 4] = vhi;
    }
}

// ---------------- persistent GRU v3: gate-paired quarters -------------------
// 768 threads: thread t owns gates (g, g+192) with g = t % 192, and h-quarter
// q = t / 192. Each h LDS.128 (warp-uniform broadcast) now feeds 4 FFMA2
// (2 gates) -> phase-1 LDS issue count halved vs v2.
// Weights: 2 gates x 32 floats = 64 floats = 32 ull = 64 regs (same as v2).
__global__ __launch_bounds__(768, 1) void k_gru(const float* __restrict__ h0,
                                                const float* __restrict__ Whh,
                                                const float* __restrict__ bhh,
                                                const float4* __restrict__ cpA,
                                                const float4* __restrict__ cpB,
                                                float2* __restrict__ cpDst) {
    if (blockIdx.x >= (Bn / 4)) {
        long j0 = (blockIdx.x - Bn / 4) * 768L + threadIdx.x;
        copy_range(cpA, cpB, cpDst, j0, N4 / 2, (long)GRUCP * 768);
        return;
    }

    __shared__ __align__(16) float h_sm[4][128];
    __shared__ float gh4[4][4][Gg];            // [row][quarter][gate]
    __shared__ float bh_sm[Gg];
    int tid = threadIdx.x;
    int b0 = blockIdx.x * 4;
    int g  = tid % 192;                        // gate in [0,192): owns g, g+192
    int q  = tid / 192;                        // h-quarter in [0,4)

    // weights: gate g quarter q (16 ull) + gate g+192 quarter q (16 ull)
    ull wA[16], wB[16];
    {
        const ulonglong2* pa = (const ulonglong2*)(Whh + g * KH + q * 32);
        const ulonglong2* pb = (const ulonglong2*)(Whh + (g + 192) * KH + q * 32);
#pragma unroll
        for (int i = 0; i < 8; i++) {
            ulonglong2 va = pa[i], vb = pb[i];
            wA[2 * i] = va.x; wA[2 * i + 1] = va.y;
            wB[2 * i] = vb.x; wB[2 * i + 1] = vb.y;
        }
    }

    if (tid < Gg) bh_sm[tid] = bhh[tid];
    int r2 = tid >> 7, j2 = tid & 127;         // valid for tid<512
    if (tid < 512) h_sm[r2][j2] = h0[(b0 + r2) * KH + j2];
    __syncthreads();

    const float* gp0 = g_gx + (size_t)(b0 + r2) * Tt * Gg;
    for (int t = 0; t < Tt; t++) {
        // prefetch this step's gx (consumed in phase 2)
        float xr = 0.f, xz = 0.f, xn = 0.f;
        if (tid < 512) {
            const float* gp = gp0 + (size_t)t * Gg;
            xr = gp[j2]; xz = gp[128 + j2]; xn = gp[256 + j2];
        }
        // phase 1: per row, quarter-dot for BOTH gates off the same h loads
#pragma unroll
        for (int r = 0; r < 4; r++) {
            ull accA = 0ULL, accB = 0ULL;
            const ulonglong2* hp = (const ulonglong2*)&h_sm[r][q * 32];
#pragma unroll
            for (int i = 0; i < 8; i++) {
                ulonglong2 hv = hp[i];           // warp-uniform broadcast
                accA = ff2(wA[2 * i],     hv.x, accA);
                accA = ff2(wA[2 * i + 1], hv.y, accA);
                accB = ff2(wB[2 * i],     hv.x, accB);
                accB = ff2(wB[2 * i + 1], hv.y, accB);
            }
            float2 sa = unpk2(accA), sb = unpk2(accB);
            gh4[r][q][g]       = sa.x + sa.y;
            gh4[r][q][g + 192] = sb.x + sb.y;
        }
        __syncthreads();
        // phase 2: combine 4 quarters, gates + state update
        if (tid < 512) {
            float hr = (gh4[r2][0][j2] + gh4[r2][1][j2])
                     + (gh4[r2][2][j2] + gh4[r2][3][j2]) + bh_sm[j2];
            float hz = (gh4[r2][0][128 + j2] + gh4[r2][1][128 + j2])
                     + (gh4[r2][2][128 + j2] + gh4[r2][3][128 + j2]) + bh_sm[128 + j2];
            float hn = (gh4[r2][0][256 + j2] + gh4[r2][1][256 + j2])
                     + (gh4[r2][2][256 + j2] + gh4[r2][3][256 + j2]) + bh_sm[256 + j2];
            float rr = fast_sigmoid(xr + hr);
            float zz = fast_sigmoid(xz + hz);
            float nn = fast_tanh(xn + rr * hn);
            float hp = h_sm[r2][j2];
            h_sm[r2][j2] = (1.f - zz) * nn + zz * hp;
        }
        __syncthreads();
    }
    if (tid < 512) g_ctT[j2 * Bn + (b0 + r2)] = h_sm[r2][j2];
}

// ------------- generic batched GEMM (round-2 proven): C=sum_k A[k][m]B[k][n]
__global__ __launch_bounds__(256) void k_gemm(const float* __restrict__ A,
                                              const float* __restrict__ Bm,
                                              float* __restrict__ C,
                                              int lda, int ldb, int ldc, int KK,
                                              long sA, long sB, long sC,
                                              const float* __restrict__ rowBias, int sBias) {
    __shared__ __align__(16) float As[32][64];
    __shared__ __align__(16) float Bs[32][128];
    int f = blockIdx.z;
    A += (long)f * sA; Bm += (long)f * sB; C += (long)f * sC;
    int tid = threadIdx.x;
    int m0 = blockIdx.y * 64, n0 = blockIdx.x * 128;
    int mA = m0 + (tid & 63), kA0 = tid >> 6;
    int nB = n0 + (tid & 127), kB0 = tid >> 7;
    int tx = tid & 31, ty = tid >> 5;
    ull acc[4][4];
#pragma unroll
    for (int i = 0; i < 4; i++)
#pragma unroll
        for (int j = 0; j < 4; j++) acc[i][j] = 0ULL;

    for (int kt = 0; kt < KK; kt += 32) {
#pragma unroll
        for (int i = 0; i < 8; i++) { int kl = kA0 + 4 * i; As[kl][tid & 63] = A[(long)(kt + kl) * lda + mA]; }
#pragma unroll
        for (int i = 0; i < 16; i++) { int kl = kB0 + 2 * i; Bs[kl][tid & 127] = Bm[(long)(kt + kl) * ldb + nB]; }
        __syncthreads();
#pragma unroll
        for (int k = 0; k < 32; k++) {
            ulonglong2 a0 = *(const ulonglong2*)&As[k][ty * 8];
            ulonglong2 a1 = *(const ulonglong2*)&As[k][ty * 8 + 4];
            float4 b4 = *(const float4*)&Bs[k][tx * 4];
            ull bb[4] = {dup2(b4.x), dup2(b4.y), dup2(b4.z), dup2(b4.w)};
            ull am[4] = {a0.x, a0.y, a1.x, a1.y};
#pragma unroll
            for (int i = 0; i < 4; i++)
#pragma unroll
                for (int j = 0; j < 4; j++) acc[i][j] = ff2(am[i], bb[j], acc[i][j]);
        }
        __syncthreads();
    }
#pragma unroll
    for (int i = 0; i < 4; i++) {
        int mlo = m0 + ty * 8 + 2 * i;
        float blo = rowBias ? rowBias[(long)f * sBias + mlo] : 0.f;
        float bhi = rowBias ? rowBias[(long)f * sBias + mlo + 1] : 0.f;
        float2 c0 = unpk2(acc[i][0]), c1 = unpk2(acc[i][1]);
        float2 c2 = unpk2(acc[i][2]), c3 = unpk2(acc[i][3]);
        float4 vlo = {c0.x + blo, c1.x + blo, c2.x + blo, c3.x + blo};
        float4 vhi = {c0.y + bhi, c1.y + bhi, c2.y + bhi, c3.y + bhi};
        *(float4*)&C[(long)mlo * ldc + n0 + tx * 4] = vlo;
        *(float4*)&C[(long)(mlo + 1) * ldc + n0 + tx * 4] = vhi;
    }
}

// ---------------- per-row logsumexp + diagonal of log_softmax --------------
__global__ void k_lse() {
    int row = blockIdx.x;                       // f*512 + b
    const float* p = g_totals + (size_t)row * Bn;
    int tid = threadIdx.x;                      // 128
    __shared__ float sm[128];
    float mx = -1e30f;
    for (int c = tid; c < Bn; c += 128) mx = fmaxf(mx, p[c]);
    sm[tid] = mx; __syncthreads();
    for (int s = 64; s; s >>= 1) { if (tid < s) sm[tid] = fmaxf(sm[tid], sm[tid + s]); __syncthreads(); }
    mx = sm[0]; __syncthreads();
    float sum = 0.f;
    for (int c = tid; c < Bn; c += 128) sum += expf(p[c] - mx);
    sm[tid] = sum; __syncthreads();
    for (int s = 64; s; s >>= 1) { if (tid < s) sm[tid] += sm[tid + s]; __syncthreads(); }
    if (tid == 0) {
        float lse = mx + logf(sm[0]);
        int b = row & 511, f = row >> 9;
        g_diag[row] = p[b] - lse;
        if (f == Ff - 1) g_lse15[b] = lse;
    }
}

// ---------------- accuracy: argmax over b of softmax column ----------------
__global__ void k_acc() {
    int c = blockIdx.x;
    const float* p = g_totals + (size_t)(Ff - 1) * Bn * Bn;
    int tid = threadIdx.x;                      // 128
    float best = -1e30f; int bi = 1 << 30;
    for (int b = tid; b < Bn; b += 128) {
        float v = p[(size_t)b * Bn + c] - g_lse15[b];
        if (v > best) { best = v; bi = b; }
    }
    __shared__ float sv[128]; __shared__ int si[128];
    sv[tid] = best; si[tid] = bi; __syncthreads();
    for (int s = 64; s; s >>= 1) {
        if (tid < s) {
            float v2 = sv[tid + s]; int i2 = si[tid + s];
            if (v2 > sv[tid] || (v2 == sv[tid] && i2 < si[tid])) { sv[tid] = v2; si[tid] = i2; }
        }
        __syncthreads();
    }
    if (tid == 0) g_ok[c] = (si[0] == c) ? 1 : 0;
}

// ---------------- deterministic final reduction -----------------------------
__global__ void k_final(float* __restrict__ out) {
    __shared__ float s[256]; __shared__ int si[256];
    int tid = threadIdx.x;
    float sum = 0.f;
    for (int i = tid; i < Ff * Bn; i += 256) sum += g_diag[i];
    int cnt = 0;
    for (int i = tid; i < Bn; i += 256) cnt += g_ok[i];
    s[tid] = sum; si[tid] = cnt; __syncthreads();
    for (int st = 128; st; st >>= 1) {
        if (tid < st) { s[tid] += s[tid + st]; si[tid] += si[tid + st]; }
        __syncthreads();
    }
    if (tid == 0) {
        out[0] = (float)si[0] / (float)Bn;               // accuracy
        out[1] = -s[0] / (float)(Ff * Bn);               // nce
    }
}

// ---------------- host ----------------
extern "C" void kernel_launch(void* const* d_in, const int* in_sizes, int n_in,
                              void* d_out, int out_size) {
    const float* zqst   = (const float*)d_in[0];
    const float* zex    = (const float*)d_in[1];
    const float* zqx    = (const float*)d_in[2];
    const float* hidden = (const float*)d_in[3];
    const float* Wih = (const float*)d_in[4];
    const float* Whh = (const float*)d_in[5];
    const float* bih = (const float*)d_in[6];
    const float* bhh = (const float*)d_in[7];
    const float* Wkw = (const float*)d_in[8];
    const float* Wkb = (const float*)d_in[9];
    float* out = (float*)d_out;

    float *p_wkT, *p_ctT, *p_predT, *p_encT, *p_totals;
    cudaGetSymbolAddress((void**)&p_wkT,    g_WkT);
    cudaGetSymbolAddress((void**)&p_ctT,    g_ctT);
    cudaGetSymbolAddress((void**)&p_predT,  g_predT);
    cudaGetSymbolAddress((void**)&p_encT,   g_encT);
    cudaGetSymbolAddress((void**)&p_totals, g_totals);

    // launch order keeps k_gru as the 4th launch (ncu captures it)
    k_transpose_wih<<<(Gg * Kd + 255) / 256, 256>>>(Wih);
    k_transpose_wk<<<(Ff * Kd * KH + 255) / 256, 256>>>(Wkw);

    // gx GEMM + second half of copy (y0) + enc gather (y1)
    k_gx<<<dim3(GXB + CPB, Gg / 128), 256>>>(zqst, bih,
        (const float4*)zex, (const float4*)zqx, (float2*)(out + 2));

    // GRU v3 + first half of passthrough copy on the 20 idle SMs
    k_gru<<<Bn / 4 + GRUCP, 768>>>(hidden, Whh, bhh,
        (const float4*)zex, (const float4*)zqx, (float2*)(out + 2));

    // predT[f][k][c] = sum_h WkT[f][h][k] * ctT[h][c] + Wk_b[f][k]
    k_gemm<<<dim3(Bn / 128, Kd / 64, Ff), 256>>>(p_wkT, p_ctT, p_predT,
        Kd, Bn, Bn, KH, (long)KH * Kd, 0L, (long)Kd * Bn, Wkb, Kd);
    // totals[f][b][c] = sum_k encT[f][k][b] * predT[f][k][c]
    k_gemm<<<dim3(Bn / 128, Bn / 64, Ff), 256>>>(p_encT, p_predT, p_totals,
        Bn, Bn, Bn, Kd, (long)Kd * Bn, (long)Kd * Bn, (long)Bn * Bn, nullptr, 0);

    k_lse<<<Ff * Bn, 128>>>();
    k_acc<<<Bn, 128>>>();
    k_final<<<1, 256>>>(out);
}